// round 10
// baseline (speedup 1.0000x reference)
#include <cuda_runtime.h>
#include <cuda_bf16.h>
#include <cstdint>

#define NTOK 1024
#define QKVOUT 1536

typedef __nv_bfloat16 bf;

// Packed bf16 hi/lo pairs (hi = low 16 bits). Same 128 MiB footprint as R9.
__device__ float g_q [16*8*NTOK*64];   // [bh][n][d]  (Q pre-scaled by 0.125)
__device__ float g_k [16*8*NTOK*64];   // [bh][n][d]
__device__ float g_vT[16*8*64*NTOK];   // [bh][d][n]
__device__ float g_ao[16*NTOK*512];    // [m][h*64+d]

__device__ __forceinline__ void bsplit(float v, bf& h, bf& l) {
    h = __float2bfloat16(v);
    l = __float2bfloat16(v - __bfloat162float(h));
}
__device__ __forceinline__ uint32_t bpack(float v) {
    bf h, l; bsplit(v, h, l);
    return (uint32_t)__bfloat16_as_ushort(h) |
           ((uint32_t)__bfloat16_as_ushort(l) << 16);
}
__device__ __forceinline__ uint32_t hpack(bf a, bf b) {
    return (uint32_t)__bfloat16_as_ushort(a) |
           ((uint32_t)__bfloat16_as_ushort(b) << 16);
}
__device__ __forceinline__ void mma_bf(float* c, const uint32_t* a,
                                       uint32_t b0, uint32_t b1) {
    asm volatile(
        "mma.sync.aligned.m16n8k16.row.col.f32.bf16.bf16.f32 "
        "{%0,%1,%2,%3}, {%4,%5,%6,%7}, {%8,%9}, {%0,%1,%2,%3};"
        : "+f"(c[0]), "+f"(c[1]), "+f"(c[2]), "+f"(c[3])
        : "r"(a[0]), "r"(a[1]), "r"(a[2]), "r"(a[3]), "r"(b0), "r"(b1));
}

// Fragment-order addressing.
// A-operand 16x16 tile (i = m-tile, ks = k-chunk): lane holds 4 regs = 16B.
//   element (row r 0..15, k-pair kk 0..7): reg = (r>>3)|((kk>>2)<<1),
//   lane = (r&7)*4 + (kk&3).
// B-operand 8n x 16k tile (j = n-tile, ks): lane holds 2 regs = 8B.
//   element (n g 0..7, kk 0..7): reg = kk>>2, lane = g*4 + (kk&3).
#define AF(base, i, ks, ln, NKS) ((base) + (((i)*(NKS)+(ks))*32 + (ln))*16)
#define BF_(base, j, ks, ln, NKS) ((base) + (((j)*(NKS)+(ks))*32 + (ln))*8)

// ============ Kernel 1: QKV projection ======================================
// frag smem: AH 0 | AL 8192 | BH 16384 | BL 24576 (32k stage, NKS=2)
// epilogue reuses as f32[128][130] = 66560
#define GEMM_SMEM 66560

__global__ __launch_bounds__(256)
void gemm_qkv(const float* __restrict__ x, const float* __restrict__ w,
              const float* __restrict__ bias)
{
    extern __shared__ char sm[];
    const int tid = threadIdx.x, wid = tid >> 5, lane = tid & 31;
    const int g = lane >> 2, tg = lane & 3;
    const int wm = wid & 3, wn = wid >> 2;
    const int m0 = blockIdx.y * 128, o0 = blockIdx.x * 128;
    const int b = m0 >> 10, n0 = m0 & 1023;
    const float* Ab = x + b * 512 * NTOK + n0;

    float acc[2][8][4];
#pragma unroll
    for (int i = 0; i < 2; i++)
#pragma unroll
        for (int j = 0; j < 8; j++)
#pragma unroll
            for (int q = 0; q < 4; q++) acc[i][j][q] = 0.f;

    for (int ck = 0; ck < 16; ck++) {
        __syncthreads();
#pragma unroll
        for (int it = 0; it < 8; it++) {              // A 128m x 16 kpairs
            int idx = tid + it * 256; int m = idx & 127, kp = idx >> 7;
            float v0 = Ab[(ck * 32 + 2 * kp) * NTOK + m];
            float v1 = Ab[(ck * 32 + 2 * kp + 1) * NTOK + m];
            bf h0, l0, h1, l1; bsplit(v0, h0, l0); bsplit(v1, h1, l1);
            int i2 = m >> 4, r = m & 15, ks = kp >> 3, kk = kp & 7;
            int reg = (r >> 3) | ((kk >> 2) << 1);
            int ls = (r & 7) * 4 + (kk & 3);
            *(uint32_t*)(sm + AF(0, i2, ks, ls, 2) + reg * 4) = hpack(h0, h1);
            *(uint32_t*)(sm + AF(8192, i2, ks, ls, 2) + reg * 4) = hpack(l0, l1);
        }
#pragma unroll
        for (int it = 0; it < 8; it++) {              // B 128o x 16 kpairs
            int idx = tid + it * 256; int oo = idx & 127, kp = idx >> 7;
            float v0 = w[(ck * 32 + 2 * kp) * QKVOUT + o0 + oo];
            float v1 = w[(ck * 32 + 2 * kp + 1) * QKVOUT + o0 + oo];
            bf h0, l0, h1, l1; bsplit(v0, h0, l0); bsplit(v1, h1, l1);
            int j2 = oo >> 3, g2 = oo & 7, ks = kp >> 3, kk = kp & 7;
            int reg = kk >> 2;
            int ls = g2 * 4 + (kk & 3);
            *(uint32_t*)(sm + BF_(16384, j2, ks, ls, 2) + reg * 4) = hpack(h0, h1);
            *(uint32_t*)(sm + BF_(24576, j2, ks, ls, 2) + reg * 4) = hpack(l0, l1);
        }
        __syncthreads();
#pragma unroll
        for (int ks = 0; ks < 2; ks++) {
            uint4 ahv[2], alv[2];
#pragma unroll
            for (int mt = 0; mt < 2; mt++) {
                int i2 = wm * 2 + mt;
                ahv[mt] = *(const uint4*)(sm + AF(0, i2, ks, lane, 2));
                alv[mt] = *(const uint4*)(sm + AF(8192, i2, ks, lane, 2));
            }
#pragma unroll
            for (int nt = 0; nt < 8; nt++) {
                int j2 = wn * 8 + nt;
                uint2 bh = *(const uint2*)(sm + BF_(16384, j2, ks, lane, 2));
                uint2 bl = *(const uint2*)(sm + BF_(24576, j2, ks, lane, 2));
#pragma unroll
                for (int mt = 0; mt < 2; mt++) {
                    mma_bf(acc[mt][nt], (const uint32_t*)&ahv[mt], bh.x, bh.y);
                    mma_bf(acc[mt][nt], (const uint32_t*)&ahv[mt], bl.x, bl.y);
                    mma_bf(acc[mt][nt], (const uint32_t*)&alv[mt], bh.x, bh.y);
                }
            }
        }
    }
    __syncthreads();
    float* stg = (float*)sm;                          // [128][130]
#pragma unroll
    for (int mt = 0; mt < 2; mt++)
#pragma unroll
        for (int nt = 0; nt < 8; nt++) {
            int r0 = wm * 32 + mt * 16 + g, c = wn * 64 + nt * 8 + 2 * tg;
            stg[r0 * 130 + c]           = acc[mt][nt][0];
            stg[r0 * 130 + c + 1]       = acc[mt][nt][1];
            stg[(r0 + 8) * 130 + c]     = acc[mt][nt][2];
            stg[(r0 + 8) * 130 + c + 1] = acc[mt][nt][3];
        }
    __syncthreads();
    for (int j = 0; j < 64; j++) {                    // q,k: lanes vary o
        int idx = tid + j * 256; int oc = idx & 127, rr = idx >> 7;
        int o = o0 + oc, head = o / 192, r2 = o - head * 192;
        if (r2 < 128) {
            float val = stg[rr * 130 + oc] + bias[o];
            if (r2 < 64) val *= 0.125f;               // fold attn scale into Q
            uint32_t* dst = (uint32_t*)((r2 < 64) ? g_q : g_k);
            dst[(((b * 8 + head) << 10) + n0 + rr) * 64 + (r2 & 63)] = bpack(val);
        }
    }
    for (int j = 0; j < 64; j++) {                    // vT: lanes vary n
        int idx = tid + j * 256; int rr = idx & 127, oc = idx >> 7;
        int o = o0 + oc, head = o / 192, r2 = o - head * 192;
        if (r2 >= 128)
            ((uint32_t*)g_vT)[((b * 8 + head) * 64 + (r2 - 128)) * 1024 + n0 + rr] =
                bpack(stg[rr * 130 + oc] + bias[o]);
    }
}

// ============ Kernel 2: attention ===========================================
// QH 0 (16384) | QL 16384 | KH 32768 (8192) | KL 40960 | VH 49152 | VL 57344
// SS f32[128][68] @65536 (34816) | PH 100352 (16384) | PL 116736 ; total 133120
#define ATTN_SMEM 133120

__global__ __launch_bounds__(256)
void attn_kernel()
{
    extern __shared__ char sm[];
    __shared__ float m_row[128], l_row[128], corr_row[128];
    float* SS = (float*)(sm + 65536);
    const int tid = threadIdx.x, wid = tid >> 5, lane = tid & 31;
    const int g = lane >> 2, tg = lane & 3;
    const int wm = wid & 3, wn = wid >> 2;
    const int bh = blockIdx.y, q0 = blockIdx.x * 128;
    const uint32_t* Qg = (const uint32_t*)g_q  + (size_t)bh * (NTOK * 64);
    const uint32_t* Kg = (const uint32_t*)g_k  + (size_t)bh * (NTOK * 64);
    const uint32_t* Vg = (const uint32_t*)g_vT + (size_t)bh * (64 * NTOK);

    if (tid < 128) { m_row[tid] = -1e30f; l_row[tid] = 0.f; }

#pragma unroll 4
    for (int it = 0; it < 16; it++) {                 // Q 128q x 32 dpairs
        int idx = tid + it * 256; int d2 = idx & 31, q = idx >> 5;
        uint2 wv = *(const uint2*)(Qg + (q0 + q) * 64 + 2 * d2);
        int i2 = q >> 4, r = q & 15, ks = d2 >> 3, kk = d2 & 7;
        int reg = (r >> 3) | ((kk >> 2) << 1);
        int ls = (r & 7) * 4 + (kk & 3);
        *(uint32_t*)(sm + AF(0, i2, ks, ls, 4) + reg * 4) = __byte_perm(wv.x, wv.y, 0x5410);
        *(uint32_t*)(sm + AF(16384, i2, ks, ls, 4) + reg * 4) = __byte_perm(wv.x, wv.y, 0x7632);
    }
    float o[2][4][4];
#pragma unroll
    for (int i = 0; i < 2; i++)
#pragma unroll
        for (int j = 0; j < 4; j++)
#pragma unroll
            for (int q = 0; q < 4; q++) o[i][j][q] = 0.f;

    for (int t = 0; t < 16; t++) {
        __syncthreads();
#pragma unroll
        for (int it = 0; it < 8; it++) {              // K 64key x 32 dpairs
            int idx = tid + it * 256; int d2 = idx & 31, rk = idx >> 5;
            uint2 wv = *(const uint2*)(Kg + (t * 64 + rk) * 64 + 2 * d2);
            int j2 = rk >> 3, g2 = rk & 7, ks = d2 >> 3, kk = d2 & 7;
            int reg = kk >> 2;
            int ls = g2 * 4 + (kk & 3);
            *(uint32_t*)(sm + BF_(32768, j2, ks, ls, 4) + reg * 4) = __byte_perm(wv.x, wv.y, 0x5410);
            *(uint32_t*)(sm + BF_(40960, j2, ks, ls, 4) + reg * 4) = __byte_perm(wv.x, wv.y, 0x7632);
        }
#pragma unroll
        for (int it = 0; it < 8; it++) {              // V 64d x 32 keypairs
            int idx = tid + it * 256; int k2 = idx & 31, d = idx >> 5;
            uint2 wv = *(const uint2*)(Vg + d * 1024 + t * 64 + 2 * k2);
            int j2 = d >> 3, g2 = d & 7, ks = k2 >> 3, kk = k2 & 7;
            int reg = kk >> 2;
            int ls = g2 * 4 + (kk & 3);
            *(uint32_t*)(sm + BF_(49152, j2, ks, ls, 4) + reg * 4) = __byte_perm(wv.x, wv.y, 0x5410);
            *(uint32_t*)(sm + BF_(57344, j2, ks, ls, 4) + reg * 4) = __byte_perm(wv.x, wv.y, 0x7632);
        }
        __syncthreads();
        float s[2][4][4];                             // S = Q K^T (Q pre-scaled)
#pragma unroll
        for (int i = 0; i < 2; i++)
#pragma unroll
            for (int j = 0; j < 4; j++)
#pragma unroll
                for (int q = 0; q < 4; q++) s[i][j][q] = 0.f;
#pragma unroll
        for (int ks = 0; ks < 4; ks++) {
            uint4 ahv[2], alv[2];
#pragma unroll
            for (int mt = 0; mt < 2; mt++) {
                int i2 = wm * 2 + mt;
                ahv[mt] = *(const uint4*)(sm + AF(0, i2, ks, lane, 4));
                alv[mt] = *(const uint4*)(sm + AF(16384, i2, ks, lane, 4));
            }
#pragma unroll
            for (int nt = 0; nt < 4; nt++) {
                int j2 = wn * 4 + nt;
                uint2 bh2 = *(const uint2*)(sm + BF_(32768, j2, ks, lane, 4));
                uint2 bl2 = *(const uint2*)(sm + BF_(40960, j2, ks, lane, 4));
#pragma unroll
                for (int mt = 0; mt < 2; mt++) {
                    mma_bf(s[mt][nt], (const uint32_t*)&ahv[mt], bh2.x, bh2.y);
                    mma_bf(s[mt][nt], (const uint32_t*)&ahv[mt], bl2.x, bl2.y);
                    mma_bf(s[mt][nt], (const uint32_t*)&alv[mt], bh2.x, bh2.y);
                }
            }
        }
#pragma unroll
        for (int mt = 0; mt < 2; mt++)
#pragma unroll
            for (int nt = 0; nt < 4; nt++) {
                int r0 = wm * 32 + mt * 16 + g, c = wn * 32 + nt * 8 + 2 * tg;
                float2 v0; v0.x = s[mt][nt][0]; v0.y = s[mt][nt][1];
                float2 v1; v1.x = s[mt][nt][2]; v1.y = s[mt][nt][3];
                *(float2*)&SS[r0 * 68 + c] = v0;
                *(float2*)&SS[(r0 + 8) * 68 + c] = v1;
            }
        __syncthreads();
        {                                             // softmax: 2 thr/row
            int row = tid >> 1, half = tid & 1, cb = half * 32;
            float mo = m_row[row];
            float lm = -1e30f;
#pragma unroll 8
            for (int i = 0; i < 32; i++) lm = fmaxf(lm, SS[row * 68 + cb + i]);
            lm = fmaxf(lm, __shfl_xor_sync(0xffffffffu, lm, 1));
            float mn = fmaxf(mo, lm);
            float corr = __expf(mo - mn);
            float ps = 0.f;
            int i2 = row >> 4, r = row & 15;
#pragma unroll 4
            for (int p = 0; p < 16; p++) {            // write P in frag order
                float p0 = __expf(SS[row * 68 + cb + 2 * p] - mn);
                float p1 = __expf(SS[row * 68 + cb + 2 * p + 1] - mn);
                bf h0, l0, h1, l1; bsplit(p0, h0, l0); bsplit(p1, h1, l1);
                ps += __bfloat162float(h0) + __bfloat162float(l0)
                    + __bfloat162float(h1) + __bfloat162float(l1);
                int kp = half * 16 + p, ks = kp >> 3, kk = kp & 7;
                int reg = (r >> 3) | ((kk >> 2) << 1);
                int ls = (r & 7) * 4 + (kk & 3);
                *(uint32_t*)(sm + AF(100352, i2, ks, ls, 4) + reg * 4) = hpack(h0, h1);
                *(uint32_t*)(sm + AF(116736, i2, ks, ls, 4) + reg * 4) = hpack(l0, l1);
            }
            ps += __shfl_xor_sync(0xffffffffu, ps, 1);
            if (half == 0) {
                m_row[row] = mn;
                l_row[row] = l_row[row] * corr + ps;
                corr_row[row] = corr;
            }
        }
        __syncthreads();
#pragma unroll
        for (int mt = 0; mt < 2; mt++) {              // rescale O
            float c0 = corr_row[wm * 32 + mt * 16 + g];
            float c1 = corr_row[wm * 32 + mt * 16 + g + 8];
#pragma unroll
            for (int nt = 0; nt < 4; nt++) {
                o[mt][nt][0] *= c0; o[mt][nt][1] *= c0;
                o[mt][nt][2] *= c1; o[mt][nt][3] *= c1;
            }
        }
#pragma unroll
        for (int ks = 0; ks < 4; ks++) {              // O += P V
            uint4 ahv[2], alv[2];
#pragma unroll
            for (int mt = 0; mt < 2; mt++) {
                int i2 = wm * 2 + mt;
                ahv[mt] = *(const uint4*)(sm + AF(100352, i2, ks, lane, 4));
                alv[mt] = *(const uint4*)(sm + AF(116736, i2, ks, lane, 4));
            }
#pragma unroll
            for (int nt = 0; nt < 4; nt++) {
                int j2 = wn * 4 + nt;
                uint2 bh2 = *(const uint2*)(sm + BF_(49152, j2, ks, lane, 4));
                uint2 bl2 = *(const uint2*)(sm + BF_(57344, j2, ks, lane, 4));
#pragma unroll
                for (int mt = 0; mt < 2; mt++) {
                    mma_bf(o[mt][nt], (const uint32_t*)&ahv[mt], bh2.x, bh2.y);
                    mma_bf(o[mt][nt], (const uint32_t*)&ahv[mt], bl2.x, bl2.y);
                    mma_bf(o[mt][nt], (const uint32_t*)&alv[mt], bh2.x, bh2.y);
                }
            }
        }
    }
    __syncthreads();
    float* ostg = SS;                                 // [128][65]
#pragma unroll
    for (int mt = 0; mt < 2; mt++) {
        int r0 = wm * 32 + mt * 16 + g;
        float i0 = 1.f / l_row[r0], i1 = 1.f / l_row[r0 + 8];
#pragma unroll
        for (int nt = 0; nt < 4; nt++) {
            int c = wn * 32 + nt * 8 + 2 * tg;
            ostg[r0 * 65 + c]           = o[mt][nt][0] * i0;
            ostg[r0 * 65 + c + 1]       = o[mt][nt][1] * i0;
            ostg[(r0 + 8) * 65 + c]     = o[mt][nt][2] * i1;
            ostg[(r0 + 8) * 65 + c + 1] = o[mt][nt][3] * i1;
        }
    }
    __syncthreads();
    const int bb = bh >> 3, hh = bh & 7;
    for (int j = 0; j < 32; j++) {
        int idx = tid + j * 256; int d = idx & 63, rr = idx >> 6;
        ((uint32_t*)g_ao)[((bb << 10) + q0 + rr) * 512 + hh * 64 + d] =
            bpack(ostg[rr * 65 + d]);
    }
}

// ============ Kernel 3: out projection + bias + residual ====================
__global__ __launch_bounds__(256)
void gemm_out(const float* __restrict__ w, const float* __restrict__ bias,
              const float* __restrict__ x, float* __restrict__ out)
{
    extern __shared__ char sm[];
    const int tid = threadIdx.x, wid = tid >> 5, lane = tid & 31;
    const int g = lane >> 2, tg = lane & 3;
    const int wm = wid & 3, wn = wid >> 2;
    const int m0 = blockIdx.y * 128, o0 = blockIdx.x * 128;
    const int b = m0 >> 10, n0 = m0 & 1023;

    float acc[2][8][4];
#pragma unroll
    for (int i = 0; i < 2; i++)
#pragma unroll
        for (int j = 0; j < 8; j++)
#pragma unroll
            for (int q = 0; q < 4; q++) acc[i][j][q] = 0.f;

    for (int ck = 0; ck < 16; ck++) {
        __syncthreads();
#pragma unroll
        for (int it = 0; it < 8; it++) {              // A from packed g_ao
            int idx = tid + it * 256; int kp = idx & 15, m = idx >> 4;
            uint2 wv = *(const uint2*)((const uint32_t*)g_ao +
                        (size_t)(m0 + m) * 512 + ck * 32 + 2 * kp);
            int i2 = m >> 4, r = m & 15, ks = kp >> 3, kk = kp & 7;
            int reg = (r >> 3) | ((kk >> 2) << 1);
            int ls = (r & 7) * 4 + (kk & 3);
            *(uint32_t*)(sm + AF(0, i2, ks, ls, 2) + reg * 4) = __byte_perm(wv.x, wv.y, 0x5410);
            *(uint32_t*)(sm + AF(8192, i2, ks, ls, 2) + reg * 4) = __byte_perm(wv.x, wv.y, 0x7632);
        }
#pragma unroll
        for (int it = 0; it < 8; it++) {              // B 128o x 16 kpairs
            int idx = tid + it * 256; int oo = idx & 127, kp = idx >> 7;
            float v0 = w[(ck * 32 + 2 * kp) * 512 + o0 + oo];
            float v1 = w[(ck * 32 + 2 * kp + 1) * 512 + o0 + oo];
            bf h0, l0, h1, l1; bsplit(v0, h0, l0); bsplit(v1, h1, l1);
            int j2 = oo >> 3, g2 = oo & 7, ks = kp >> 3, kk = kp & 7;
            int reg = kk >> 2;
            int ls = g2 * 4 + (kk & 3);
            *(uint32_t*)(sm + BF_(16384, j2, ks, ls, 2) + reg * 4) = hpack(h0, h1);
            *(uint32_t*)(sm + BF_(24576, j2, ks, ls, 2) + reg * 4) = hpack(l0, l1);
        }
        __syncthreads();
#pragma unroll
        for (int ks = 0; ks < 2; ks++) {
            uint4 ahv[2], alv[2];
#pragma unroll
            for (int mt = 0; mt < 2; mt++) {
                int i2 = wm * 2 + mt;
                ahv[mt] = *(const uint4*)(sm + AF(0, i2, ks, lane, 2));
                alv[mt] = *(const uint4*)(sm + AF(8192, i2, ks, lane, 2));
            }
#pragma unroll
            for (int nt = 0; nt < 8; nt++) {
                int j2 = wn * 8 + nt;
                uint2 bh2 = *(const uint2*)(sm + BF_(16384, j2, ks, lane, 2));
                uint2 bl2 = *(const uint2*)(sm + BF_(24576, j2, ks, lane, 2));
#pragma unroll
                for (int mt = 0; mt < 2; mt++) {
                    mma_bf(acc[mt][nt], (const uint32_t*)&ahv[mt], bh2.x, bh2.y);
                    mma_bf(acc[mt][nt], (const uint32_t*)&ahv[mt], bl2.x, bl2.y);
                    mma_bf(acc[mt][nt], (const uint32_t*)&alv[mt], bh2.x, bh2.y);
                }
            }
        }
    }
    __syncthreads();
    float* stg = (float*)sm;                          // [128][130]
#pragma unroll
    for (int mt = 0; mt < 2; mt++)
#pragma unroll
        for (int nt = 0; nt < 8; nt++) {
            int r0 = wm * 32 + mt * 16 + g, c = wn * 64 + nt * 8 + 2 * tg;
            stg[r0 * 130 + c]           = acc[mt][nt][0];
            stg[r0 * 130 + c + 1]       = acc[mt][nt][1];
            stg[(r0 + 8) * 130 + c]     = acc[mt][nt][2];
            stg[(r0 + 8) * 130 + c + 1] = acc[mt][nt][3];
        }
    __syncthreads();
    for (int j = 0; j < 64; j++) {                    // lanes vary n
        int idx = tid + j * 256; int rr = idx & 127, oc = idx >> 7;
        int oo = o0 + oc;
        int gi = ((b * 512 + oo) << 10) + n0 + rr;
        out[gi] = stg[rr * 130 + oc] + bias[oo] + x[gi];
    }
}

// ---------------------------------------------------------------------------
extern "C" void kernel_launch(void* const* d_in, const int* in_sizes, int n_in,
                              void* d_out, int out_size)
{
    const float* x      = (const float*)d_in[0];
    const float* w_proj = (const float*)d_in[1];
    const float* b_proj = (const float*)d_in[2];
    const float* w_out  = (const float*)d_in[3];
    const float* b_out  = (const float*)d_in[4];
    float* out = (float*)d_out;

    cudaFuncSetAttribute(gemm_qkv,    cudaFuncAttributeMaxDynamicSharedMemorySize, GEMM_SMEM);
    cudaFuncSetAttribute(attn_kernel, cudaFuncAttributeMaxDynamicSharedMemorySize, ATTN_SMEM);
    cudaFuncSetAttribute(gemm_out,    cudaFuncAttributeMaxDynamicSharedMemorySize, GEMM_SMEM);

    gemm_qkv<<<dim3(12, 128), 256, GEMM_SMEM>>>(x, w_proj, b_proj);
    attn_kernel<<<dim3(8, 128), 256, ATTN_SMEM>>>();
    gemm_out<<<dim3(4, 128), 256, GEMM_SMEM>>>(w_out, b_out, x, out);
}

// round 12
// speedup vs baseline: 1.1930x; 1.1930x over previous
#include <cuda_runtime.h>
#include <cuda_bf16.h>
#include <cstdint>

#define NTOK 1024
#define QKVOUT 1536

typedef __nv_bfloat16 bf;

// Packed bf16 hi/lo pairs (hi = low 16 bits). Same 128 MiB footprint as R9.
__device__ float g_q [16*8*NTOK*64];   // [bh][n][d]  (Q pre-scaled by 0.125)
__device__ float g_k [16*8*NTOK*64];   // [bh][n][d]
__device__ float g_vT[16*8*64*NTOK];   // [bh][d][n]
__device__ float g_ao[16*NTOK*512];    // [m][h*64+d]

__device__ __forceinline__ void bsplit(float v, bf& h, bf& l) {
    h = __float2bfloat16(v);
    l = __float2bfloat16(v - __bfloat162float(h));
}
__device__ __forceinline__ uint32_t bpack(float v) {
    bf h, l; bsplit(v, h, l);
    return (uint32_t)__bfloat16_as_ushort(h) |
           ((uint32_t)__bfloat16_as_ushort(l) << 16);
}
__device__ __forceinline__ uint32_t hpack(bf a, bf b) {
    return (uint32_t)__bfloat16_as_ushort(a) |
           ((uint32_t)__bfloat16_as_ushort(b) << 16);
}
__device__ __forceinline__ void mma_bf(float* c, const uint32_t* a,
                                       uint32_t b0, uint32_t b1) {
    asm volatile(
        "mma.sync.aligned.m16n8k16.row.col.f32.bf16.bf16.f32 "
        "{%0,%1,%2,%3}, {%4,%5,%6,%7}, {%8,%9}, {%0,%1,%2,%3};"
        : "+f"(c[0]), "+f"(c[1]), "+f"(c[2]), "+f"(c[3])
        : "r"(a[0]), "r"(a[1]), "r"(a[2]), "r"(a[3]), "r"(b0), "r"(b1));
}

// Fragment-order addressing:
// A tile: lane holds 4 regs = 16B; elem (r, kk): reg=(r>>3)|((kk>>2)<<1),
//   lane=(r&7)*4+(kk&3). B tile: lane holds 2 regs = 8B; reg=kk>>2, lane=g*4+(kk&3).
#define AF(base, i, ks, ln, NKS) ((base) + (((i)*(NKS)+(ks))*32 + (ln))*16)
#define BF_(base, j, ks, ln, NKS) ((base) + (((j)*(NKS)+(ks))*32 + (ln))*8)

// ============ Kernel 1: QKV projection ======================================
// frag smem: AH 0 | AL 8192 | BH 16384 | BL 24576 (32k stage, NKS=2)
// epilogue reuses as f32[128][130] = 66560
#define GEMM_SMEM 66560

__global__ __launch_bounds__(256, 2)
void gemm_qkv(const float* __restrict__ x, const float* __restrict__ w,
              const float* __restrict__ bias)
{
    extern __shared__ char sm[];
    const int tid = threadIdx.x, wid = tid >> 5, lane = tid & 31;
    const int g = lane >> 2, tg = lane & 3;
    const int wm = wid & 3, wn = wid >> 2;
    const int m0 = blockIdx.y * 128, o0 = blockIdx.x * 128;
    const int b = m0 >> 10, n0 = m0 & 1023;
    const float* Ab = x + b * 512 * NTOK + n0;

    float acc[2][8][4];
#pragma unroll
    for (int i = 0; i < 2; i++)
#pragma unroll
        for (int j = 0; j < 8; j++)
#pragma unroll
            for (int q = 0; q < 4; q++) acc[i][j][q] = 0.f;

    for (int ck = 0; ck < 16; ck++) {
        __syncthreads();
#pragma unroll
        for (int it = 0; it < 8; it++) {              // A 128m x 16 kpairs
            int idx = tid + it * 256; int m = idx & 127, kp = idx >> 7;
            float v0 = Ab[(ck * 32 + 2 * kp) * NTOK + m];
            float v1 = Ab[(ck * 32 + 2 * kp + 1) * NTOK + m];
            bf h0, l0, h1, l1; bsplit(v0, h0, l0); bsplit(v1, h1, l1);
            int i2 = m >> 4, r = m & 15, ks = kp >> 3, kk = kp & 7;
            int reg = (r >> 3) | ((kk >> 2) << 1);
            int ls = (r & 7) * 4 + (kk & 3);
            *(uint32_t*)(sm + AF(0, i2, ks, ls, 2) + reg * 4) = hpack(h0, h1);
            *(uint32_t*)(sm + AF(8192, i2, ks, ls, 2) + reg * 4) = hpack(l0, l1);
        }
#pragma unroll
        for (int it = 0; it < 8; it++) {              // B 128o x 16 kpairs
            int idx = tid + it * 256; int oo = idx & 127, kp = idx >> 7;
            float v0 = w[(ck * 32 + 2 * kp) * QKVOUT + o0 + oo];
            float v1 = w[(ck * 32 + 2 * kp + 1) * QKVOUT + o0 + oo];
            bf h0, l0, h1, l1; bsplit(v0, h0, l0); bsplit(v1, h1, l1);
            int j2 = oo >> 3, g2 = oo & 7, ks = kp >> 3, kk = kp & 7;
            int reg = kk >> 2;
            int ls = g2 * 4 + (kk & 3);
            *(uint32_t*)(sm + BF_(16384, j2, ks, ls, 2) + reg * 4) = hpack(h0, h1);
            *(uint32_t*)(sm + BF_(24576, j2, ks, ls, 2) + reg * 4) = hpack(l0, l1);
        }
        __syncthreads();
#pragma unroll
        for (int ks = 0; ks < 2; ks++) {
            uint4 ahv[2], alv[2];
#pragma unroll
            for (int mt = 0; mt < 2; mt++) {
                int i2 = wm * 2 + mt;
                ahv[mt] = *(const uint4*)(sm + AF(0, i2, ks, lane, 2));
                alv[mt] = *(const uint4*)(sm + AF(8192, i2, ks, lane, 2));
            }
#pragma unroll
            for (int nt = 0; nt < 8; nt++) {
                int j2 = wn * 8 + nt;
                uint2 bh = *(const uint2*)(sm + BF_(16384, j2, ks, lane, 2));
                uint2 bl = *(const uint2*)(sm + BF_(24576, j2, ks, lane, 2));
#pragma unroll
                for (int mt = 0; mt < 2; mt++) {
                    mma_bf(acc[mt][nt], (const uint32_t*)&ahv[mt], bh.x, bh.y);
                    mma_bf(acc[mt][nt], (const uint32_t*)&ahv[mt], bl.x, bl.y);
                    mma_bf(acc[mt][nt], (const uint32_t*)&alv[mt], bh.x, bh.y);
                }
            }
        }
    }
    __syncthreads();
    float* stg = (float*)sm;                          // [128][130]
#pragma unroll
    for (int mt = 0; mt < 2; mt++)
#pragma unroll
        for (int nt = 0; nt < 8; nt++) {
            int r0 = wm * 32 + mt * 16 + g, c = wn * 64 + nt * 8 + 2 * tg;
            stg[r0 * 130 + c]           = acc[mt][nt][0];
            stg[r0 * 130 + c + 1]       = acc[mt][nt][1];
            stg[(r0 + 8) * 130 + c]     = acc[mt][nt][2];
            stg[(r0 + 8) * 130 + c + 1] = acc[mt][nt][3];
        }
    __syncthreads();
    for (int j = 0; j < 64; j++) {                    // q,k: lanes vary o
        int idx = tid + j * 256; int oc = idx & 127, rr = idx >> 7;
        int o = o0 + oc, head = o / 192, r2 = o - head * 192;
        if (r2 < 128) {
            float val = stg[rr * 130 + oc] + bias[o];
            if (r2 < 64) val *= 0.125f;               // fold attn scale into Q
            uint32_t* dst = (uint32_t*)((r2 < 64) ? g_q : g_k);
            dst[(((b * 8 + head) << 10) + n0 + rr) * 64 + (r2 & 63)] = bpack(val);
        }
    }
    for (int j = 0; j < 64; j++) {                    // vT: lanes vary n
        int idx = tid + j * 256; int rr = idx & 127, oc = idx >> 7;
        int o = o0 + oc, head = o / 192, r2 = o - head * 192;
        if (r2 >= 128)
            ((uint32_t*)g_vT)[((b * 8 + head) * 64 + (r2 - 128)) * 1024 + n0 + rr] =
                bpack(stg[rr * 130 + oc] + bias[o]);
    }
}

// ============ Kernel 2: attention ===========================================
// QH 0 (16384) | QL 16384 | KH 32768 (8192) | KL 40960 | VH 49152 | VL 57344
// SS f32[128][68] @65536 (34816) | PH 100352 (16384) | PL 116736 ; total 133120
#define ATTN_SMEM 133120

__global__ __launch_bounds__(256, 1)
void attn_kernel()
{
    extern __shared__ char sm[];
    __shared__ float m_row[128], l_row[128], corr_row[128];
    float* SS = (float*)(sm + 65536);
    const int tid = threadIdx.x, wid = tid >> 5, lane = tid & 31;
    const int g = lane >> 2, tg = lane & 3;
    const int wm = wid & 3, wn = wid >> 2;
    const int bh = blockIdx.y, q0 = blockIdx.x * 128;
    const uint32_t* Qg = (const uint32_t*)g_q  + (size_t)bh * (NTOK * 64);
    const uint32_t* Kg = (const uint32_t*)g_k  + (size_t)bh * (NTOK * 64);
    const uint32_t* Vg = (const uint32_t*)g_vT + (size_t)bh * (64 * NTOK);

    if (tid < 128) { m_row[tid] = -1e30f; l_row[tid] = 0.f; }

#pragma unroll 4
    for (int it = 0; it < 16; it++) {                 // Q 128q x 32 dpairs
        int idx = tid + it * 256; int d2 = idx & 31, q = idx >> 5;
        uint2 wv = *(const uint2*)(Qg + (q0 + q) * 64 + 2 * d2);
        int i2 = q >> 4, r = q & 15, ks = d2 >> 3, kk = d2 & 7;
        int reg = (r >> 3) | ((kk >> 2) << 1);
        int ls = (r & 7) * 4 + (kk & 3);
        *(uint32_t*)(sm + AF(0, i2, ks, ls, 4) + reg * 4) = __byte_perm(wv.x, wv.y, 0x5410);
        *(uint32_t*)(sm + AF(16384, i2, ks, ls, 4) + reg * 4) = __byte_perm(wv.x, wv.y, 0x7632);
    }
    float o[2][4][4];
#pragma unroll
    for (int i = 0; i < 2; i++)
#pragma unroll
        for (int j = 0; j < 4; j++)
#pragma unroll
            for (int q = 0; q < 4; q++) o[i][j][q] = 0.f;

    for (int t = 0; t < 16; t++) {
        __syncthreads();
#pragma unroll
        for (int it = 0; it < 8; it++) {              // K 64key x 32 dpairs
            int idx = tid + it * 256; int d2 = idx & 31, rk = idx >> 5;
            uint2 wv = *(const uint2*)(Kg + (t * 64 + rk) * 64 + 2 * d2);
            int j2 = rk >> 3, g2 = rk & 7, ks = d2 >> 3, kk = d2 & 7;
            int reg = kk >> 2;
            int ls = g2 * 4 + (kk & 3);
            *(uint32_t*)(sm + BF_(32768, j2, ks, ls, 4) + reg * 4) = __byte_perm(wv.x, wv.y, 0x5410);
            *(uint32_t*)(sm + BF_(40960, j2, ks, ls, 4) + reg * 4) = __byte_perm(wv.x, wv.y, 0x7632);
        }
#pragma unroll
        for (int it = 0; it < 8; it++) {              // V 64d x 32 keypairs
            int idx = tid + it * 256; int k2 = idx & 31, d = idx >> 5;
            uint2 wv = *(const uint2*)(Vg + d * 1024 + t * 64 + 2 * k2);
            int j2 = d >> 3, g2 = d & 7, ks = k2 >> 3, kk = k2 & 7;
            int reg = kk >> 2;
            int ls = g2 * 4 + (kk & 3);
            *(uint32_t*)(sm + BF_(49152, j2, ks, ls, 4) + reg * 4) = __byte_perm(wv.x, wv.y, 0x5410);
            *(uint32_t*)(sm + BF_(57344, j2, ks, ls, 4) + reg * 4) = __byte_perm(wv.x, wv.y, 0x7632);
        }
        __syncthreads();
        float s[2][4][4];                             // S = Q K^T (Q pre-scaled)
#pragma unroll
        for (int i = 0; i < 2; i++)
#pragma unroll
            for (int j = 0; j < 4; j++)
#pragma unroll
                for (int q = 0; q < 4; q++) s[i][j][q] = 0.f;
#pragma unroll
        for (int ks = 0; ks < 4; ks++) {
            uint4 ahv[2], alv[2];
#pragma unroll
            for (int mt = 0; mt < 2; mt++) {
                int i2 = wm * 2 + mt;
                ahv[mt] = *(const uint4*)(sm + AF(0, i2, ks, lane, 4));
                alv[mt] = *(const uint4*)(sm + AF(16384, i2, ks, lane, 4));
            }
#pragma unroll
            for (int nt = 0; nt < 4; nt++) {
                int j2 = wn * 4 + nt;
                uint2 bh2 = *(const uint2*)(sm + BF_(32768, j2, ks, lane, 4));
                uint2 bl2 = *(const uint2*)(sm + BF_(40960, j2, ks, lane, 4));
#pragma unroll
                for (int mt = 0; mt < 2; mt++) {
                    mma_bf(s[mt][nt], (const uint32_t*)&ahv[mt], bh2.x, bh2.y);
                    mma_bf(s[mt][nt], (const uint32_t*)&ahv[mt], bl2.x, bl2.y);
                    mma_bf(s[mt][nt], (const uint32_t*)&alv[mt], bh2.x, bh2.y);
                }
            }
        }
#pragma unroll
        for (int mt = 0; mt < 2; mt++)
#pragma unroll
            for (int nt = 0; nt < 4; nt++) {
                int r0 = wm * 32 + mt * 16 + g, c = wn * 32 + nt * 8 + 2 * tg;
                float2 v0; v0.x = s[mt][nt][0]; v0.y = s[mt][nt][1];
                float2 v1; v1.x = s[mt][nt][2]; v1.y = s[mt][nt][3];
                *(float2*)&SS[r0 * 68 + c] = v0;
                *(float2*)&SS[(r0 + 8) * 68 + c] = v1;
            }
        __syncthreads();
        {                                             // softmax: 2 thr/row
            int row = tid >> 1, half = tid & 1, cb = half * 32;
            float mo = m_row[row];
            float lm = -1e30f;
#pragma unroll 8
            for (int i = 0; i < 32; i++) lm = fmaxf(lm, SS[row * 68 + cb + i]);
            lm = fmaxf(lm, __shfl_xor_sync(0xffffffffu, lm, 1));
            float mn = fmaxf(mo, lm);
            float corr = __expf(mo - mn);
            float ps = 0.f;
            int i2 = row >> 4, r = row & 15;
#pragma unroll 4
            for (int p = 0; p < 16; p++) {            // write P in frag order
                float p0 = __expf(SS[row * 68 + cb + 2 * p] - mn);
                float p1 = __expf(SS[row * 68 + cb + 2 * p + 1] - mn);
                bf h0, l0, h1, l1; bsplit(p0, h0, l0); bsplit(p1, h1, l1);
                ps += __bfloat162float(h0) + __bfloat162float(l0)
                    + __bfloat162float(h1) + __bfloat162float(l1);
                int kp = half * 16 + p, ks = kp >> 3, kk = kp & 7;
                int reg = (r >> 3) | ((kk >> 2) << 1);
                int ls = (r & 7) * 4 + (kk & 3);
                *(uint32_t*)(sm + AF(100352, i2, ks, ls, 4) + reg * 4) = hpack(h0, h1);
                *(uint32_t*)(sm + AF(116736, i2, ks, ls, 4) + reg * 4) = hpack(l0, l1);
            }
            ps += __shfl_xor_sync(0xffffffffu, ps, 1);
            if (half == 0) {
                m_row[row] = mn;
                l_row[row] = l_row[row] * corr + ps;
                corr_row[row] = corr;
            }
        }
        __syncthreads();
#pragma unroll
        for (int mt = 0; mt < 2; mt++) {              // rescale O
            float c0 = corr_row[wm * 32 + mt * 16 + g];
            float c1 = corr_row[wm * 32 + mt * 16 + g + 8];
#pragma unroll
            for (int nt = 0; nt < 4; nt++) {
                o[mt][nt][0] *= c0; o[mt][nt][1] *= c0;
                o[mt][nt][2] *= c1; o[mt][nt][3] *= c1;
            }
        }
#pragma unroll
        for (int ks = 0; ks < 4; ks++) {              // O += P V
            uint4 ahv[2], alv[2];
#pragma unroll
            for (int mt = 0; mt < 2; mt++) {
                int i2 = wm * 2 + mt;
                ahv[mt] = *(const uint4*)(sm + AF(100352, i2, ks, lane, 4));
                alv[mt] = *(const uint4*)(sm + AF(116736, i2, ks, lane, 4));
            }
#pragma unroll
            for (int nt = 0; nt < 4; nt++) {
                int j2 = wn * 4 + nt;
                uint2 bh2 = *(const uint2*)(sm + BF_(49152, j2, ks, lane, 4));
                uint2 bl2 = *(const uint2*)(sm + BF_(57344, j2, ks, lane, 4));
#pragma unroll
                for (int mt = 0; mt < 2; mt++) {
                    mma_bf(o[mt][nt], (const uint32_t*)&ahv[mt], bh2.x, bh2.y);
                    mma_bf(o[mt][nt], (const uint32_t*)&ahv[mt], bl2.x, bl2.y);
                    mma_bf(o[mt][nt], (const uint32_t*)&alv[mt], bh2.x, bh2.y);
                }
            }
        }
    }
    __syncthreads();
    float* ostg = SS;                                 // [128][65]
#pragma unroll
    for (int mt = 0; mt < 2; mt++) {
        int r0 = wm * 32 + mt * 16 + g;
        float i0 = 1.f / l_row[r0], i1 = 1.f / l_row[r0 + 8];
#pragma unroll
        for (int nt = 0; nt < 4; nt++) {
            int c = wn * 32 + nt * 8 + 2 * tg;
            ostg[r0 * 65 + c]           = o[mt][nt][0] * i0;
            ostg[r0 * 65 + c + 1]       = o[mt][nt][1] * i0;
            ostg[(r0 + 8) * 65 + c]     = o[mt][nt][2] * i1;
            ostg[(r0 + 8) * 65 + c + 1] = o[mt][nt][3] * i1;
        }
    }
    __syncthreads();
    const int bb = bh >> 3, hh = bh & 7;
    for (int j = 0; j < 32; j++) {
        int idx = tid + j * 256; int d = idx & 63, rr = idx >> 6;
        ((uint32_t*)g_ao)[((bb << 10) + q0 + rr) * 512 + hh * 64 + d] =
            bpack(ostg[rr * 65 + d]);
    }
}

// ============ Kernel 3: out projection + bias + residual ====================
__global__ __launch_bounds__(256, 2)
void gemm_out(const float* __restrict__ w, const float* __restrict__ bias,
              const float* __restrict__ x, float* __restrict__ out)
{
    extern __shared__ char sm[];
    const int tid = threadIdx.x, wid = tid >> 5, lane = tid & 31;
    const int g = lane >> 2, tg = lane & 3;
    const int wm = wid & 3, wn = wid >> 2;
    const int m0 = blockIdx.y * 128, o0 = blockIdx.x * 128;
    const int b = m0 >> 10, n0 = m0 & 1023;

    float acc[2][8][4];
#pragma unroll
    for (int i = 0; i < 2; i++)
#pragma unroll
        for (int j = 0; j < 8; j++)
#pragma unroll
            for (int q = 0; q < 4; q++) acc[i][j][q] = 0.f;

    for (int ck = 0; ck < 16; ck++) {
        __syncthreads();
#pragma unroll
        for (int it = 0; it < 8; it++) {              // A from packed g_ao
            int idx = tid + it * 256; int kp = idx & 15, m = idx >> 4;
            uint2 wv = *(const uint2*)((const uint32_t*)g_ao +
                        (size_t)(m0 + m) * 512 + ck * 32 + 2 * kp);
            int i2 = m >> 4, r = m & 15, ks = kp >> 3, kk = kp & 7;
            int reg = (r >> 3) | ((kk >> 2) << 1);
            int ls = (r & 7) * 4 + (kk & 3);
            *(uint32_t*)(sm + AF(0, i2, ks, ls, 2) + reg * 4) = __byte_perm(wv.x, wv.y, 0x5410);
            *(uint32_t*)(sm + AF(8192, i2, ks, ls, 2) + reg * 4) = __byte_perm(wv.x, wv.y, 0x7632);
        }
#pragma unroll
        for (int it = 0; it < 8; it++) {              // B 128o x 16 kpairs
            int idx = tid + it * 256; int oo = idx & 127, kp = idx >> 7;
            float v0 = w[(ck * 32 + 2 * kp) * 512 + o0 + oo];
            float v1 = w[(ck * 32 + 2 * kp + 1) * 512 + o0 + oo];
            bf h0, l0, h1, l1; bsplit(v0, h0, l0); bsplit(v1, h1, l1);
            int j2 = oo >> 3, g2 = oo & 7, ks = kp >> 3, kk = kp & 7;
            int reg = kk >> 2;
            int ls = g2 * 4 + (kk & 3);
            *(uint32_t*)(sm + BF_(16384, j2, ks, ls, 2) + reg * 4) = hpack(h0, h1);
            *(uint32_t*)(sm + BF_(24576, j2, ks, ls, 2) + reg * 4) = hpack(l0, l1);
        }
        __syncthreads();
#pragma unroll
        for (int ks = 0; ks < 2; ks++) {
            uint4 ahv[2], alv[2];
#pragma unroll
            for (int mt = 0; mt < 2; mt++) {
                int i2 = wm * 2 + mt;
                ahv[mt] = *(const uint4*)(sm + AF(0, i2, ks, lane, 2));
                alv[mt] = *(const uint4*)(sm + AF(8192, i2, ks, lane, 2));
            }
#pragma unroll
            for (int nt = 0; nt < 8; nt++) {
                int j2 = wn * 8 + nt;
                uint2 bh2 = *(const uint2*)(sm + BF_(16384, j2, ks, lane, 2));
                uint2 bl2 = *(const uint2*)(sm + BF_(24576, j2, ks, lane, 2));
#pragma unroll
                for (int mt = 0; mt < 2; mt++) {
                    mma_bf(acc[mt][nt], (const uint32_t*)&ahv[mt], bh2.x, bh2.y);
                    mma_bf(acc[mt][nt], (const uint32_t*)&ahv[mt], bl2.x, bl2.y);
                    mma_bf(acc[mt][nt], (const uint32_t*)&alv[mt], bh2.x, bh2.y);
                }
            }
        }
    }
    __syncthreads();
    float* stg = (float*)sm;                          // [128][130]
#pragma unroll
    for (int mt = 0; mt < 2; mt++)
#pragma unroll
        for (int nt = 0; nt < 8; nt++) {
            int r0 = wm * 32 + mt * 16 + g, c = wn * 64 + nt * 8 + 2 * tg;
            stg[r0 * 130 + c]           = acc[mt][nt][0];
            stg[r0 * 130 + c + 1]       = acc[mt][nt][1];
            stg[(r0 + 8) * 130 + c]     = acc[mt][nt][2];
            stg[(r0 + 8) * 130 + c + 1] = acc[mt][nt][3];
        }
    __syncthreads();
    for (int j = 0; j < 64; j++) {                    // lanes vary n
        int idx = tid + j * 256; int rr = idx & 127, oc = idx >> 7;
        int oo = o0 + oc;
        int gi = ((b * 512 + oo) << 10) + n0 + rr;
        out[gi] = stg[rr * 130 + oc] + bias[oo] + x[gi];
    }
}

// ---------------------------------------------------------------------------
extern "C" void kernel_launch(void* const* d_in, const int* in_sizes, int n_in,
                              void* d_out, int out_size)
{
    const float* x      = (const float*)d_in[0];
    const float* w_proj = (const float*)d_in[1];
    const float* b_proj = (const float*)d_in[2];
    const float* w_out  = (const float*)d_in[3];
    const float* b_out  = (const float*)d_in[4];
    float* out = (float*)d_out;

    cudaFuncSetAttribute(gemm_qkv,    cudaFuncAttributeMaxDynamicSharedMemorySize, GEMM_SMEM);
    cudaFuncSetAttribute(attn_kernel, cudaFuncAttributeMaxDynamicSharedMemorySize, ATTN_SMEM);
    cudaFuncSetAttribute(gemm_out,    cudaFuncAttributeMaxDynamicSharedMemorySize, GEMM_SMEM);

    gemm_qkv<<<dim3(12, 128), 256, GEMM_SMEM>>>(x, w_proj, b_proj);
    attn_kernel<<<dim3(8, 128), 256, ATTN_SMEM>>>();
    gemm_out<<<dim3(4, 128), 256, GEMM_SMEM>>>(w_out, b_out, x, out);
}

// round 15
// speedup vs baseline: 1.3416x; 1.1245x over previous
#include <cuda_runtime.h>
#include <cuda_bf16.h>
#include <cstdint>

#define NTOK 1024
#define QKVOUT 1536

typedef __nv_bfloat16 bf;

// Packed bf16 hi/lo pairs (hi = low 16 bits). Same 128 MiB footprint as R9.
__device__ float g_q [16*8*NTOK*64];   // [bh][n][d]  (Q pre-scaled by 0.125)
__device__ float g_k [16*8*NTOK*64];   // [bh][n][d]
__device__ float g_vT[16*8*64*NTOK];   // [bh][d][n]
__device__ float g_ao[16*NTOK*512];    // [m][h*64+d]

__device__ __forceinline__ void bsplit(float v, bf& h, bf& l) {
    h = __float2bfloat16(v);
    l = __float2bfloat16(v - __bfloat162float(h));
}
__device__ __forceinline__ uint32_t bpack(float v) {
    bf h, l; bsplit(v, h, l);
    return (uint32_t)__bfloat16_as_ushort(h) |
           ((uint32_t)__bfloat16_as_ushort(l) << 16);
}
__device__ __forceinline__ uint32_t hpack(bf a, bf b) {
    return (uint32_t)__bfloat16_as_ushort(a) |
           ((uint32_t)__bfloat16_as_ushort(b) << 16);
}
__device__ __forceinline__ void mma_bf(float* c, const uint32_t* a,
                                       uint32_t b0, uint32_t b1) {
    asm volatile(
        "mma.sync.aligned.m16n8k16.row.col.f32.bf16.bf16.f32 "
        "{%0,%1,%2,%3}, {%4,%5,%6,%7}, {%8,%9}, {%0,%1,%2,%3};"
        : "+f"(c[0]), "+f"(c[1]), "+f"(c[2]), "+f"(c[3])
        : "r"(a[0]), "r"(a[1]), "r"(a[2]), "r"(a[3]), "r"(b0), "r"(b1));
}

// Fragment-order addressing with bank swizzle.
// slot ls (0..31): j = ls>>2, c = ls&3. FSWZ = (j XOR 2c) | (c<<3).
//   - producer stores (j varies, c fixed): chunk index (FSWZ mod 8) is a
//     bijection in j -> conflict-free-ish (<=2-way).
//   - consumer LDS.128/64 (8/16-lane phases): FSWZ mod 8/16 distinct -> clean.
// A tile stride 512B (32 slots x 16B); B tile stride 264B (32 slots x 8B + 8 pad).
#define FSWZ(ls) ((((ls) >> 2) ^ ((((ls) & 3) << 1) & 7)) | (((ls) & 3) << 3))
#define AF(base, i, ks, ln, NKS) ((base) + ((i)*(NKS)+(ks))*512 + FSWZ(ln)*16)
#define BF_(base, j, ks, ln, NKS) ((base) + ((j)*(NKS)+(ks))*264 + FSWZ(ln)*8)

// ============ Kernel 1: QKV projection ======================================
// frag smem: AH 0 (8192) | AL 8192 | BH 16384 (8448) | BL 24832 ; end 33280
// epilogue reuses as f32[128][130] = 66560
#define GEMM_SMEM 66560

__global__ __launch_bounds__(256, 2)
void gemm_qkv(const float* __restrict__ x, const float* __restrict__ w,
              const float* __restrict__ bias)
{
    extern __shared__ char sm[];
    const int tid = threadIdx.x, wid = tid >> 5, lane = tid & 31;
    const int g = lane >> 2, tg = lane & 3;
    const int wm = wid & 3, wn = wid >> 2;
    const int m0 = blockIdx.y * 128, o0 = blockIdx.x * 128;
    const int b = m0 >> 10, n0 = m0 & 1023;
    const float* Ab = x + b * 512 * NTOK + n0;

    float acc[2][8][4];
#pragma unroll
    for (int i = 0; i < 2; i++)
#pragma unroll
        for (int j = 0; j < 8; j++)
#pragma unroll
            for (int q = 0; q < 4; q++) acc[i][j][q] = 0.f;

    for (int ck = 0; ck < 16; ck++) {
        __syncthreads();
#pragma unroll
        for (int it = 0; it < 8; it++) {              // A 128m x 16 kpairs
            int idx = tid + it * 256; int m = idx & 127, kp = idx >> 7;
            float v0 = Ab[(ck * 32 + 2 * kp) * NTOK + m];
            float v1 = Ab[(ck * 32 + 2 * kp + 1) * NTOK + m];
            bf h0, l0, h1, l1; bsplit(v0, h0, l0); bsplit(v1, h1, l1);
            int i2 = m >> 4, r = m & 15, ks = kp >> 3, kk = kp & 7;
            int reg = (r >> 3) | ((kk >> 2) << 1);
            int ls = (r & 7) * 4 + (kk & 3);
            *(uint32_t*)(sm + AF(0, i2, ks, ls, 2) + reg * 4) = hpack(h0, h1);
            *(uint32_t*)(sm + AF(8192, i2, ks, ls, 2) + reg * 4) = hpack(l0, l1);
        }
#pragma unroll
        for (int it = 0; it < 8; it++) {              // B 128o x 16 kpairs
            int idx = tid + it * 256; int oo = idx & 127, kp = idx >> 7;
            float v0 = w[(ck * 32 + 2 * kp) * QKVOUT + o0 + oo];
            float v1 = w[(ck * 32 + 2 * kp + 1) * QKVOUT + o0 + oo];
            bf h0, l0, h1, l1; bsplit(v0, h0, l0); bsplit(v1, h1, l1);
            int j2 = oo >> 3, g2 = oo & 7, ks = kp >> 3, kk = kp & 7;
            int reg = kk >> 2;
            int ls = g2 * 4 + (kk & 3);
            *(uint32_t*)(sm + BF_(16384, j2, ks, ls, 2) + reg * 4) = hpack(h0, h1);
            *(uint32_t*)(sm + BF_(24832, j2, ks, ls, 2) + reg * 4) = hpack(l0, l1);
        }
        __syncthreads();
#pragma unroll
        for (int ks = 0; ks < 2; ks++) {
            uint4 ahv[2], alv[2];
#pragma unroll
            for (int mt = 0; mt < 2; mt++) {
                int i2 = wm * 2 + mt;
                ahv[mt] = *(const uint4*)(sm + AF(0, i2, ks, lane, 2));
                alv[mt] = *(const uint4*)(sm + AF(8192, i2, ks, lane, 2));
            }
#pragma unroll
            for (int nt = 0; nt < 8; nt++) {
                int j2 = wn * 8 + nt;
                uint2 bh = *(const uint2*)(sm + BF_(16384, j2, ks, lane, 2));
                uint2 bl = *(const uint2*)(sm + BF_(24832, j2, ks, lane, 2));
#pragma unroll
                for (int mt = 0; mt < 2; mt++) {
                    mma_bf(acc[mt][nt], (const uint32_t*)&ahv[mt], bh.x, bh.y);
                    mma_bf(acc[mt][nt], (const uint32_t*)&ahv[mt], bl.x, bl.y);
                    mma_bf(acc[mt][nt], (const uint32_t*)&alv[mt], bh.x, bh.y);
                }
            }
        }
    }
    __syncthreads();
    float* stg = (float*)sm;                          // [128][130]
#pragma unroll
    for (int mt = 0; mt < 2; mt++)
#pragma unroll
        for (int nt = 0; nt < 8; nt++) {
            int r0 = wm * 32 + mt * 16 + g, c = wn * 64 + nt * 8 + 2 * tg;
            stg[r0 * 130 + c]           = acc[mt][nt][0];
            stg[r0 * 130 + c + 1]       = acc[mt][nt][1];
            stg[(r0 + 8) * 130 + c]     = acc[mt][nt][2];
            stg[(r0 + 8) * 130 + c + 1] = acc[mt][nt][3];
        }
    __syncthreads();
    for (int j = 0; j < 64; j++) {                    // q,k: lanes vary o
        int idx = tid + j * 256; int oc = idx & 127, rr = idx >> 7;
        int o = o0 + oc, head = o / 192, r2 = o - head * 192;
        if (r2 < 128) {
            float val = stg[rr * 130 + oc] + bias[o];
            if (r2 < 64) val *= 0.125f;               // fold attn scale into Q
            uint32_t* dst = (uint32_t*)((r2 < 64) ? g_q : g_k);
            dst[(((b * 8 + head) << 10) + n0 + rr) * 64 + (r2 & 63)] = bpack(val);
        }
    }
    for (int j = 0; j < 64; j++) {                    // vT: lanes vary n
        int idx = tid + j * 256; int rr = idx & 127, oc = idx >> 7;
        int o = o0 + oc, head = o / 192, r2 = o - head * 192;
        if (r2 >= 128)
            ((uint32_t*)g_vT)[((b * 8 + head) * 64 + (r2 - 128)) * 1024 + n0 + rr] =
                bpack(stg[rr * 130 + oc] + bias[o]);
    }
}

// ============ Kernel 2: attention ===========================================
// QH 0 (16384) | QL 16384 | KH 32768 (8448) | KL 41216 | VH 49664 | VL 58112
// SS f32[128][68] @66560 (34816) | PH 101376 (16384) | PL 117760 ; total 134144
#define ATTN_SMEM 134144

__global__ __launch_bounds__(256, 1)
void attn_kernel()
{
    extern __shared__ char sm[];
    __shared__ float m_row[128], l_row[128], corr_row[128];
    float* SS = (float*)(sm + 66560);
    const int tid = threadIdx.x, wid = tid >> 5, lane = tid & 31;
    const int g = lane >> 2, tg = lane & 3;
    const int wm = wid & 3, wn = wid >> 2;
    const int bh = blockIdx.y, q0 = blockIdx.x * 128;
    const uint32_t* Qg = (const uint32_t*)g_q  + (size_t)bh * (NTOK * 64);
    const uint32_t* Kg = (const uint32_t*)g_k  + (size_t)bh * (NTOK * 64);
    const uint32_t* Vg = (const uint32_t*)g_vT + (size_t)bh * (64 * NTOK);

    if (tid < 128) { m_row[tid] = -1e30f; l_row[tid] = 0.f; }

#pragma unroll 4
    for (int it = 0; it < 16; it++) {                 // Q 128q x 32 dpairs
        int idx = tid + it * 256; int d2 = idx & 31, q = idx >> 5;
        uint2 wv = *(const uint2*)(Qg + (q0 + q) * 64 + 2 * d2);
        int i2 = q >> 4, r = q & 15, ks = d2 >> 3, kk = d2 & 7;
        int reg = (r >> 3) | ((kk >> 2) << 1);
        int ls = (r & 7) * 4 + (kk & 3);
        *(uint32_t*)(sm + AF(0, i2, ks, ls, 4) + reg * 4) = __byte_perm(wv.x, wv.y, 0x5410);
        *(uint32_t*)(sm + AF(16384, i2, ks, ls, 4) + reg * 4) = __byte_perm(wv.x, wv.y, 0x7632);
    }
    float o[2][4][4];
#pragma unroll
    for (int i = 0; i < 2; i++)
#pragma unroll
        for (int j = 0; j < 4; j++)
#pragma unroll
            for (int q = 0; q < 4; q++) o[i][j][q] = 0.f;

    for (int t = 0; t < 16; t++) {
        __syncthreads();
#pragma unroll
        for (int it = 0; it < 8; it++) {              // K 64key x 32 dpairs
            int idx = tid + it * 256; int d2 = idx & 31, rk = idx >> 5;
            uint2 wv = *(const uint2*)(Kg + (t * 64 + rk) * 64 + 2 * d2);
            int j2 = rk >> 3, g2 = rk & 7, ks = d2 >> 3, kk = d2 & 7;
            int reg = kk >> 2;
            int ls = g2 * 4 + (kk & 3);
            *(uint32_t*)(sm + BF_(32768, j2, ks, ls, 4) + reg * 4) = __byte_perm(wv.x, wv.y, 0x5410);
            *(uint32_t*)(sm + BF_(41216, j2, ks, ls, 4) + reg * 4) = __byte_perm(wv.x, wv.y, 0x7632);
        }
#pragma unroll
        for (int it = 0; it < 8; it++) {              // V 64d x 32 keypairs
            int idx = tid + it * 256; int k2 = idx & 31, d = idx >> 5;
            uint2 wv = *(const uint2*)(Vg + d * 1024 + t * 64 + 2 * k2);
            int j2 = d >> 3, g2 = d & 7, ks = k2 >> 3, kk = k2 & 7;
            int reg = kk >> 2;
            int ls = g2 * 4 + (kk & 3);
            *(uint32_t*)(sm + BF_(49664, j2, ks, ls, 4) + reg * 4) = __byte_perm(wv.x, wv.y, 0x5410);
            *(uint32_t*)(sm + BF_(58112, j2, ks, ls, 4) + reg * 4) = __byte_perm(wv.x, wv.y, 0x7632);
        }
        __syncthreads();
        float s[2][4][4];                             // S = Q K^T (Q pre-scaled)
#pragma unroll
        for (int i = 0; i < 2; i++)
#pragma unroll
            for (int j = 0; j < 4; j++)
#pragma unroll
                for (int q = 0; q < 4; q++) s[i][j][q] = 0.f;
#pragma unroll
        for (int ks = 0; ks < 4; ks++) {
            uint4 ahv[2], alv[2];
#pragma unroll
            for (int mt = 0; mt < 2; mt++) {
                int i2 = wm * 2 + mt;
                ahv[mt] = *(const uint4*)(sm + AF(0, i2, ks, lane, 4));
                alv[mt] = *(const uint4*)(sm + AF(16384, i2, ks, lane, 4));
            }
#pragma unroll
            for (int nt = 0; nt < 4; nt++) {
                int j2 = wn * 4 + nt;
                uint2 bh2 = *(const uint2*)(sm + BF_(32768, j2, ks, lane, 4));
                uint2 bl2 = *(const uint2*)(sm + BF_(41216, j2, ks, lane, 4));
#pragma unroll
                for (int mt = 0; mt < 2; mt++) {
                    mma_bf(s[mt][nt], (const uint32_t*)&ahv[mt], bh2.x, bh2.y);
                    mma_bf(s[mt][nt], (const uint32_t*)&ahv[mt], bl2.x, bl2.y);
                    mma_bf(s[mt][nt], (const uint32_t*)&alv[mt], bh2.x, bh2.y);
                }
            }
        }
#pragma unroll
        for (int mt = 0; mt < 2; mt++)
#pragma unroll
            for (int nt = 0; nt < 4; nt++) {
                int r0 = wm * 32 + mt * 16 + g, c = wn * 32 + nt * 8 + 2 * tg;
                float2 v0; v0.x = s[mt][nt][0]; v0.y = s[mt][nt][1];
                float2 v1; v1.x = s[mt][nt][2]; v1.y = s[mt][nt][3];
                *(float2*)&SS[r0 * 68 + c] = v0;
                *(float2*)&SS[(r0 + 8) * 68 + c] = v1;
            }
        __syncthreads();
        {                                             // softmax: 2 thr/row
            int row = tid >> 1, half = tid & 1, cb = half * 32;
            float mo = m_row[row];
            float lm = -1e30f;
#pragma unroll 8
            for (int i = 0; i < 32; i++) lm = fmaxf(lm, SS[row * 68 + cb + i]);
            lm = fmaxf(lm, __shfl_xor_sync(0xffffffffu, lm, 1));
            float mn = fmaxf(mo, lm);
            float corr = __expf(mo - mn);
            float ps = 0.f;
            int i2 = row >> 4, r = row & 15;
#pragma unroll 4
            for (int p = 0; p < 16; p++) {            // write P in frag order
                float p0 = __expf(SS[row * 68 + cb + 2 * p] - mn);
                float p1 = __expf(SS[row * 68 + cb + 2 * p + 1] - mn);
                bf h0, l0, h1, l1; bsplit(p0, h0, l0); bsplit(p1, h1, l1);
                ps += __bfloat162float(h0) + __bfloat162float(l0)
                    + __bfloat162float(h1) + __bfloat162float(l1);
                int kp = half * 16 + p, ks = kp >> 3, kk = kp & 7;
                int reg = (r >> 3) | ((kk >> 2) << 1);
                int ls = (r & 7) * 4 + (kk & 3);
                *(uint32_t*)(sm + AF(101376, i2, ks, ls, 4) + reg * 4) = hpack(h0, h1);
                *(uint32_t*)(sm + AF(117760, i2, ks, ls, 4) + reg * 4) = hpack(l0, l1);
            }
            ps += __shfl_xor_sync(0xffffffffu, ps, 1);
            if (half == 0) {
                m_row[row] = mn;
                l_row[row] = l_row[row] * corr + ps;
                corr_row[row] = corr;
            }
        }
        __syncthreads();
#pragma unroll
        for (int mt = 0; mt < 2; mt++) {              // rescale O
            float c0 = corr_row[wm * 32 + mt * 16 + g];
            float c1 = corr_row[wm * 32 + mt * 16 + g + 8];
#pragma unroll
            for (int nt = 0; nt < 4; nt++) {
                o[mt][nt][0] *= c0; o[mt][nt][1] *= c0;
                o[mt][nt][2] *= c1; o[mt][nt][3] *= c1;
            }
        }
#pragma unroll
        for (int ks = 0; ks < 4; ks++) {              // O += P V
            uint4 ahv[2], alv[2];
#pragma unroll
            for (int mt = 0; mt < 2; mt++) {
                int i2 = wm * 2 + mt;
                ahv[mt] = *(const uint4*)(sm + AF(101376, i2, ks, lane, 4));
                alv[mt] = *(const uint4*)(sm + AF(117760, i2, ks, lane, 4));
            }
#pragma unroll
            for (int nt = 0; nt < 4; nt++) {
                int j2 = wn * 4 + nt;
                uint2 bh2 = *(const uint2*)(sm + BF_(49664, j2, ks, lane, 4));
                uint2 bl2 = *(const uint2*)(sm + BF_(58112, j2, ks, lane, 4));
#pragma unroll
                for (int mt = 0; mt < 2; mt++) {
                    mma_bf(o[mt][nt], (const uint32_t*)&ahv[mt], bh2.x, bh2.y);
                    mma_bf(o[mt][nt], (const uint32_t*)&ahv[mt], bl2.x, bl2.y);
                    mma_bf(o[mt][nt], (const uint32_t*)&alv[mt], bh2.x, bh2.y);
                }
            }
        }
    }
    __syncthreads();
    float* ostg = SS;                                 // [128][65]
#pragma unroll
    for (int mt = 0; mt < 2; mt++) {
        int r0 = wm * 32 + mt * 16 + g;
        float i0 = 1.f / l_row[r0], i1 = 1.f / l_row[r0 + 8];
#pragma unroll
        for (int nt = 0; nt < 4; nt++) {
            int c = wn * 32 + nt * 8 + 2 * tg;
            ostg[r0 * 65 + c]           = o[mt][nt][0] * i0;
            ostg[r0 * 65 + c + 1]       = o[mt][nt][1] * i0;
            ostg[(r0 + 8) * 65 + c]     = o[mt][nt][2] * i1;
            ostg[(r0 + 8) * 65 + c + 1] = o[mt][nt][3] * i1;
        }
    }
    __syncthreads();
    const int bb = bh >> 3, hh = bh & 7;
    for (int j = 0; j < 32; j++) {
        int idx = tid + j * 256; int d = idx & 63, rr = idx >> 6;
        ((uint32_t*)g_ao)[((bb << 10) + q0 + rr) * 512 + hh * 64 + d] =
            bpack(ostg[rr * 65 + d]);
    }
}

// ============ Kernel 3: out projection + bias + residual ====================
__global__ __launch_bounds__(256, 2)
void gemm_out(const float* __restrict__ w, const float* __restrict__ bias,
              const float* __restrict__ x, float* __restrict__ out)
{
    extern __shared__ char sm[];
    const int tid = threadIdx.x, wid = tid >> 5, lane = tid & 31;
    const int g = lane >> 2, tg = lane & 3;
    const int wm = wid & 3, wn = wid >> 2;
    const int m0 = blockIdx.y * 128, o0 = blockIdx.x * 128;
    const int b = m0 >> 10, n0 = m0 & 1023;

    float acc[2][8][4];
#pragma unroll
    for (int i = 0; i < 2; i++)
#pragma unroll
        for (int j = 0; j < 8; j++)
#pragma unroll
            for (int q = 0; q < 4; q++) acc[i][j][q] = 0.f;

    for (int ck = 0; ck < 16; ck++) {
        __syncthreads();
#pragma unroll
        for (int it = 0; it < 8; it++) {              // A from packed g_ao
            int idx = tid + it * 256; int kp = idx & 15, m = idx >> 4;
            uint2 wv = *(const uint2*)((const uint32_t*)g_ao +
                        (size_t)(m0 + m) * 512 + ck * 32 + 2 * kp);
            int i2 = m >> 4, r = m & 15, ks = kp >> 3, kk = kp & 7;
            int reg = (r >> 3) | ((kk >> 2) << 1);
            int ls = (r & 7) * 4 + (kk & 3);
            *(uint32_t*)(sm + AF(0, i2, ks, ls, 2) + reg * 4) = __byte_perm(wv.x, wv.y, 0x5410);
            *(uint32_t*)(sm + AF(8192, i2, ks, ls, 2) + reg * 4) = __byte_perm(wv.x, wv.y, 0x7632);
        }
#pragma unroll
        for (int it = 0; it < 8; it++) {              // B 128o x 16 kpairs
            int idx = tid + it * 256; int oo = idx & 127, kp = idx >> 7;
            float v0 = w[(ck * 32 + 2 * kp) * 512 + o0 + oo];
            float v1 = w[(ck * 32 + 2 * kp + 1) * 512 + o0 + oo];
            bf h0, l0, h1, l1; bsplit(v0, h0, l0); bsplit(v1, h1, l1);
            int j2 = oo >> 3, g2 = oo & 7, ks = kp >> 3, kk = kp & 7;
            int reg = kk >> 2;
            int ls = g2 * 4 + (kk & 3);
            *(uint32_t*)(sm + BF_(16384, j2, ks, ls, 2) + reg * 4) = hpack(h0, h1);
            *(uint32_t*)(sm + BF_(24832, j2, ks, ls, 2) + reg * 4) = hpack(l0, l1);
        }
        __syncthreads();
#pragma unroll
        for (int ks = 0; ks < 2; ks++) {
            uint4 ahv[2], alv[2];
#pragma unroll
            for (int mt = 0; mt < 2; mt++) {
                int i2 = wm * 2 + mt;
                ahv[mt] = *(const uint4*)(sm + AF(0, i2, ks, lane, 2));
                alv[mt] = *(const uint4*)(sm + AF(8192, i2, ks, lane, 2));
            }
#pragma unroll
            for (int nt = 0; nt < 8; nt++) {
                int j2 = wn * 8 + nt;
                uint2 bh2 = *(const uint2*)(sm + BF_(16384, j2, ks, lane, 2));
                uint2 bl2 = *(const uint2*)(sm + BF_(24832, j2, ks, lane, 2));
#pragma unroll
                for (int mt = 0; mt < 2; mt++) {
                    mma_bf(acc[mt][nt], (const uint32_t*)&ahv[mt], bh2.x, bh2.y);
                    mma_bf(acc[mt][nt], (const uint32_t*)&ahv[mt], bl2.x, bl2.y);
                    mma_bf(acc[mt][nt], (const uint32_t*)&alv[mt], bh2.x, bh2.y);
                }
            }
        }
    }
    __syncthreads();
    float* stg = (float*)sm;                          // [128][130]
#pragma unroll
    for (int mt = 0; mt < 2; mt++)
#pragma unroll
        for (int nt = 0; nt < 8; nt++) {
            int r0 = wm * 32 + mt * 16 + g, c = wn * 64 + nt * 8 + 2 * tg;
            stg[r0 * 130 + c]           = acc[mt][nt][0];
            stg[r0 * 130 + c + 1]       = acc[mt][nt][1];
            stg[(r0 + 8) * 130 + c]     = acc[mt][nt][2];
            stg[(r0 + 8) * 130 + c + 1] = acc[mt][nt][3];
        }
    __syncthreads();
    for (int j = 0; j < 64; j++) {                    // lanes vary n
        int idx = tid + j * 256; int rr = idx & 127, oc = idx >> 7;
        int oo = o0 + oc;
        int gi = ((b * 512 + oo) << 10) + n0 + rr;
        out[gi] = stg[rr * 130 + oc] + bias[oo] + x[gi];
    }
}

// ---------------------------------------------------------------------------
extern "C" void kernel_launch(void* const* d_in, const int* in_sizes, int n_in,
                              void* d_out, int out_size)
{
    const float* x      = (const float*)d_in[0];
    const float* w_proj = (const float*)d_in[1];
    const float* b_proj = (const float*)d_in[2];
    const float* w_out  = (const float*)d_in[3];
    const float* b_out  = (const float*)d_in[4];
    float* out = (float*)d_out;

    cudaFuncSetAttribute(gemm_qkv,    cudaFuncAttributeMaxDynamicSharedMemorySize, GEMM_SMEM);
    cudaFuncSetAttribute(attn_kernel, cudaFuncAttributeMaxDynamicSharedMemorySize, ATTN_SMEM);
    cudaFuncSetAttribute(gemm_out,    cudaFuncAttributeMaxDynamicSharedMemorySize, GEMM_SMEM);

    gemm_qkv<<<dim3(12, 128), 256, GEMM_SMEM>>>(x, w_proj, b_proj);
    attn_kernel<<<dim3(8, 128), 256, ATTN_SMEM>>>();
    gemm_out<<<dim3(4, 128), 256, GEMM_SMEM>>>(w_out, b_out, x, out);
}

// round 16
// speedup vs baseline: 1.4670x; 1.0934x over previous
#include <cuda_runtime.h>
#include <cuda_bf16.h>
#include <cstdint>

#define NTOK 1024
#define QKVOUT 1536

typedef __nv_bfloat16 bf;

__device__ float g_q [16*8*NTOK*64];   // packed bf16 hi/lo; Q pre-scaled 0.125
__device__ float g_k [16*8*NTOK*64];
__device__ float g_vT[16*8*64*NTOK];
__device__ float g_ao[16*NTOK*512];

__device__ __forceinline__ void bsplit(float v, bf& h, bf& l) {
    h = __float2bfloat16(v);
    l = __float2bfloat16(v - __bfloat162float(h));
}
__device__ __forceinline__ uint32_t bpack(float v) {
    bf h, l; bsplit(v, h, l);
    return (uint32_t)__bfloat16_as_ushort(h) |
           ((uint32_t)__bfloat16_as_ushort(l) << 16);
}
__device__ __forceinline__ uint32_t hpack(bf a, bf b) {
    return (uint32_t)__bfloat16_as_ushort(a) |
           ((uint32_t)__bfloat16_as_ushort(b) << 16);
}
__device__ __forceinline__ void mma_bf(float* c, const uint32_t* a,
                                       uint32_t b0, uint32_t b1) {
    asm volatile(
        "mma.sync.aligned.m16n8k16.row.col.f32.bf16.bf16.f32 "
        "{%0,%1,%2,%3}, {%4,%5,%6,%7}, {%8,%9}, {%0,%1,%2,%3};"
        : "+f"(c[0]), "+f"(c[1]), "+f"(c[2]), "+f"(c[3])
        : "r"(a[0]), "r"(a[1]), "r"(a[2]), "r"(a[3]), "r"(b0), "r"(b1));
}

// Fragment-order smem with bank swizzle (validated R15).
#define FSWZ(ls) ((((ls) >> 2) ^ ((((ls) & 3) << 1) & 7)) | (((ls) & 3) << 3))
#define AF(base, i, ks, ln, NKS) ((base) + ((i)*(NKS)+(ks))*512 + FSWZ(ln)*16)
#define BF_(base, j, ks, ln, NKS) ((base) + ((j)*(NKS)+(ks))*264 + FSWZ(ln)*8)

// ============ Kernel 1: QKV projection (identical to R15) ===================
#define GEMM_SMEM 66560

__global__ __launch_bounds__(256, 2)
void gemm_qkv(const float* __restrict__ x, const float* __restrict__ w,
              const float* __restrict__ bias)
{
    extern __shared__ char sm[];
    const int tid = threadIdx.x, wid = tid >> 5, lane = tid & 31;
    const int g = lane >> 2, tg = lane & 3;
    const int wm = wid & 3, wn = wid >> 2;
    const int m0 = blockIdx.y * 128, o0 = blockIdx.x * 128;
    const int b = m0 >> 10, n0 = m0 & 1023;
    const float* Ab = x + b * 512 * NTOK + n0;

    float acc[2][8][4];
#pragma unroll
    for (int i = 0; i < 2; i++)
#pragma unroll
        for (int j = 0; j < 8; j++)
#pragma unroll
            for (int q = 0; q < 4; q++) acc[i][j][q] = 0.f;

    for (int ck = 0; ck < 16; ck++) {
        __syncthreads();
#pragma unroll
        for (int it = 0; it < 8; it++) {
            int idx = tid + it * 256; int m = idx & 127, kp = idx >> 7;
            float v0 = Ab[(ck * 32 + 2 * kp) * NTOK + m];
            float v1 = Ab[(ck * 32 + 2 * kp + 1) * NTOK + m];
            bf h0, l0, h1, l1; bsplit(v0, h0, l0); bsplit(v1, h1, l1);
            int i2 = m >> 4, r = m & 15, ks = kp >> 3, kk = kp & 7;
            int reg = (r >> 3) | ((kk >> 2) << 1);
            int ls = (r & 7) * 4 + (kk & 3);
            *(uint32_t*)(sm + AF(0, i2, ks, ls, 2) + reg * 4) = hpack(h0, h1);
            *(uint32_t*)(sm + AF(8192, i2, ks, ls, 2) + reg * 4) = hpack(l0, l1);
        }
#pragma unroll
        for (int it = 0; it < 8; it++) {
            int idx = tid + it * 256; int oo = idx & 127, kp = idx >> 7;
            float v0 = w[(ck * 32 + 2 * kp) * QKVOUT + o0 + oo];
            float v1 = w[(ck * 32 + 2 * kp + 1) * QKVOUT + o0 + oo];
            bf h0, l0, h1, l1; bsplit(v0, h0, l0); bsplit(v1, h1, l1);
            int j2 = oo >> 3, g2 = oo & 7, ks = kp >> 3, kk = kp & 7;
            int reg = kk >> 2;
            int ls = g2 * 4 + (kk & 3);
            *(uint32_t*)(sm + BF_(16384, j2, ks, ls, 2) + reg * 4) = hpack(h0, h1);
            *(uint32_t*)(sm + BF_(24832, j2, ks, ls, 2) + reg * 4) = hpack(l0, l1);
        }
        __syncthreads();
#pragma unroll
        for (int ks = 0; ks < 2; ks++) {
            uint4 ahv[2], alv[2];
#pragma unroll
            for (int mt = 0; mt < 2; mt++) {
                int i2 = wm * 2 + mt;
                ahv[mt] = *(const uint4*)(sm + AF(0, i2, ks, lane, 2));
                alv[mt] = *(const uint4*)(sm + AF(8192, i2, ks, lane, 2));
            }
#pragma unroll
            for (int nt = 0; nt < 8; nt++) {
                int j2 = wn * 8 + nt;
                uint2 bh = *(const uint2*)(sm + BF_(16384, j2, ks, lane, 2));
                uint2 bl = *(const uint2*)(sm + BF_(24832, j2, ks, lane, 2));
#pragma unroll
                for (int mt = 0; mt < 2; mt++) {
                    mma_bf(acc[mt][nt], (const uint32_t*)&ahv[mt], bh.x, bh.y);
                    mma_bf(acc[mt][nt], (const uint32_t*)&ahv[mt], bl.x, bl.y);
                    mma_bf(acc[mt][nt], (const uint32_t*)&alv[mt], bh.x, bh.y);
                }
            }
        }
    }
    __syncthreads();
    float* stg = (float*)sm;
#pragma unroll
    for (int mt = 0; mt < 2; mt++)
#pragma unroll
        for (int nt = 0; nt < 8; nt++) {
            int r0 = wm * 32 + mt * 16 + g, c = wn * 64 + nt * 8 + 2 * tg;
            stg[r0 * 130 + c]           = acc[mt][nt][0];
            stg[r0 * 130 + c + 1]       = acc[mt][nt][1];
            stg[(r0 + 8) * 130 + c]     = acc[mt][nt][2];
            stg[(r0 + 8) * 130 + c + 1] = acc[mt][nt][3];
        }
    __syncthreads();
    for (int j = 0; j < 64; j++) {
        int idx = tid + j * 256; int oc = idx & 127, rr = idx >> 7;
        int o = o0 + oc, head = o / 192, r2 = o - head * 192;
        if (r2 < 128) {
            float val = stg[rr * 130 + oc] + bias[o];
            if (r2 < 64) val *= 0.125f;
            uint32_t* dst = (uint32_t*)((r2 < 64) ? g_q : g_k);
            dst[(((b * 8 + head) << 10) + n0 + rr) * 64 + (r2 & 63)] = bpack(val);
        }
    }
    for (int j = 0; j < 64; j++) {
        int idx = tid + j * 256; int rr = idx & 127, oc = idx >> 7;
        int o = o0 + oc, head = o / 192, r2 = o - head * 192;
        if (r2 >= 128)
            ((uint32_t*)g_vT)[((b * 8 + head) * 64 + (r2 - 128)) * 1024 + n0 + rr] =
                bpack(stg[rr * 130 + oc] + bias[o]);
    }
}

// ============ Kernel 2: attention (register-resident S and P) ===============
// QH 0 (16384) | QL 16384 | KH 32768 (8448) | KL 41216 | VH 49664 | VL 58112
#define ATTN_SMEM 66560

__global__ __launch_bounds__(256, 1)
void attn_kernel()
{
    extern __shared__ char sm[];
    __shared__ float m_row[128], l_row[128];
    __shared__ float smax[2][128], ssum[2][128];
    const int tid = threadIdx.x, wid = tid >> 5, lane = tid & 31;
    const int g = lane >> 2, tg = lane & 3;
    const int wm = wid & 3, wn = wid >> 2;
    const int bh = blockIdx.y, q0 = blockIdx.x * 128;
    const uint32_t* Qg = (const uint32_t*)g_q  + (size_t)bh * 65536;
    const uint32_t* Kg = (const uint32_t*)g_k  + (size_t)bh * 65536;
    const uint32_t* Vg = (const uint32_t*)g_vT + (size_t)bh * 65536;

    if (tid < 128) { m_row[tid] = -1e30f; l_row[tid] = 0.f; }

#pragma unroll 4
    for (int it = 0; it < 16; it++) {                 // Q 128q x 32 dpairs
        int idx = tid + it * 256; int d2 = idx & 31, q = idx >> 5;
        uint2 wv = *(const uint2*)(Qg + (q0 + q) * 64 + 2 * d2);
        int i2 = q >> 4, r = q & 15, ks = d2 >> 3, kk = d2 & 7;
        int reg = (r >> 3) | ((kk >> 2) << 1);
        int ls = (r & 7) * 4 + (kk & 3);
        *(uint32_t*)(sm + AF(0, i2, ks, ls, 4) + reg * 4) = __byte_perm(wv.x, wv.y, 0x5410);
        *(uint32_t*)(sm + AF(16384, i2, ks, ls, 4) + reg * 4) = __byte_perm(wv.x, wv.y, 0x7632);
    }
    float o[2][8][4];
#pragma unroll
    for (int i = 0; i < 2; i++)
#pragma unroll
        for (int j = 0; j < 8; j++)
#pragma unroll
            for (int q = 0; q < 4; q++) o[i][j][q] = 0.f;

    const int row0 = wm * 32 + g;                      // rows: row0+16*mt+8*h

    for (int t = 0; t < 16; t++) {
        __syncthreads();
#pragma unroll
        for (int it = 0; it < 8; it++) {              // K 64key x 32 dpairs
            int idx = tid + it * 256; int d2 = idx & 31, rk = idx >> 5;
            uint2 wv = *(const uint2*)(Kg + (t * 64 + rk) * 64 + 2 * d2);
            int j2 = rk >> 3, g2 = rk & 7, ks = d2 >> 3, kk = d2 & 7;
            int reg = kk >> 2;
            int ls = g2 * 4 + (kk & 3);
            *(uint32_t*)(sm + BF_(32768, j2, ks, ls, 4) + reg * 4) = __byte_perm(wv.x, wv.y, 0x5410);
            *(uint32_t*)(sm + BF_(41216, j2, ks, ls, 4) + reg * 4) = __byte_perm(wv.x, wv.y, 0x7632);
        }
#pragma unroll
        for (int it = 0; it < 8; it++) {              // V 64d x 32 keypairs
            int idx = tid + it * 256; int k2 = idx & 31, d = idx >> 5;
            uint2 wv = *(const uint2*)(Vg + d * 1024 + t * 64 + 2 * k2);
            int j2 = d >> 3, g2 = d & 7, ks = k2 >> 3, kk = k2 & 7;
            int reg = kk >> 2;
            int ls = g2 * 4 + (kk & 3);
            *(uint32_t*)(sm + BF_(49664, j2, ks, ls, 4) + reg * 4) = __byte_perm(wv.x, wv.y, 0x5410);
            *(uint32_t*)(sm + BF_(58112, j2, ks, ls, 4) + reg * 4) = __byte_perm(wv.x, wv.y, 0x7632);
        }
        __syncthreads();

        float mo[2][2];
#pragma unroll
        for (int mt = 0; mt < 2; mt++) {
            mo[mt][0] = m_row[row0 + mt * 16];
            mo[mt][1] = m_row[row0 + mt * 16 + 8];
        }

        float s[2][4][4];                             // S = Q K^T (Q pre-scaled)
#pragma unroll
        for (int i = 0; i < 2; i++)
#pragma unroll
            for (int j = 0; j < 4; j++)
#pragma unroll
                for (int q = 0; q < 4; q++) s[i][j][q] = 0.f;
#pragma unroll
        for (int ks = 0; ks < 4; ks++) {
            uint4 ahv[2], alv[2];
#pragma unroll
            for (int mt = 0; mt < 2; mt++) {
                int i2 = wm * 2 + mt;
                ahv[mt] = *(const uint4*)(sm + AF(0, i2, ks, lane, 4));
                alv[mt] = *(const uint4*)(sm + AF(16384, i2, ks, lane, 4));
            }
#pragma unroll
            for (int nt = 0; nt < 4; nt++) {
                int j2 = wn * 4 + nt;
                uint2 bh2 = *(const uint2*)(sm + BF_(32768, j2, ks, lane, 4));
                uint2 bl2 = *(const uint2*)(sm + BF_(41216, j2, ks, lane, 4));
#pragma unroll
                for (int mt = 0; mt < 2; mt++) {
                    mma_bf(s[mt][nt], (const uint32_t*)&ahv[mt], bh2.x, bh2.y);
                    mma_bf(s[mt][nt], (const uint32_t*)&ahv[mt], bl2.x, bl2.y);
                    mma_bf(s[mt][nt], (const uint32_t*)&alv[mt], bh2.x, bh2.y);
                }
            }
        }

        // row max over this warp-group's 32 keys
        float rmax[2][2];
#pragma unroll
        for (int mt = 0; mt < 2; mt++) {
            float a = s[mt][0][0], bq = s[mt][0][2];
#pragma unroll
            for (int nt = 0; nt < 4; nt++) {
                a  = fmaxf(a,  fmaxf(s[mt][nt][0], s[mt][nt][1]));
                bq = fmaxf(bq, fmaxf(s[mt][nt][2], s[mt][nt][3]));
            }
            a  = fmaxf(a,  __shfl_xor_sync(0xffffffffu, a, 1));
            a  = fmaxf(a,  __shfl_xor_sync(0xffffffffu, a, 2));
            bq = fmaxf(bq, __shfl_xor_sync(0xffffffffu, bq, 1));
            bq = fmaxf(bq, __shfl_xor_sync(0xffffffffu, bq, 2));
            rmax[mt][0] = a; rmax[mt][1] = bq;
        }
        if (tg == 0) {
#pragma unroll
            for (int mt = 0; mt < 2; mt++) {
                smax[wn][row0 + mt * 16]     = rmax[mt][0];
                smax[wn][row0 + mt * 16 + 8] = rmax[mt][1];
            }
        }
        __syncthreads();

        float mn[2][2], corr[2][2], rsum[2][2];
#pragma unroll
        for (int mt = 0; mt < 2; mt++)
#pragma unroll
            for (int h = 0; h < 2; h++) {
                int row = row0 + mt * 16 + h * 8;
                float mm = fmaxf(mo[mt][h], fmaxf(smax[0][row], smax[1][row]));
                mn[mt][h] = mm;
                corr[mt][h] = __expf(mo[mt][h] - mm);
                rsum[mt][h] = 0.f;
            }

        uint32_t php[2][4][2], plp[2][4][2];
#pragma unroll
        for (int mt = 0; mt < 2; mt++)
#pragma unroll
            for (int nt = 0; nt < 4; nt++) {
                float p0 = __expf(s[mt][nt][0] - mn[mt][0]);
                float p1 = __expf(s[mt][nt][1] - mn[mt][0]);
                float p2 = __expf(s[mt][nt][2] - mn[mt][1]);
                float p3 = __expf(s[mt][nt][3] - mn[mt][1]);
                bf h0, l0, h1, l1, h2, l2, h3, l3;
                bsplit(p0, h0, l0); bsplit(p1, h1, l1);
                bsplit(p2, h2, l2); bsplit(p3, h3, l3);
                rsum[mt][0] += __bfloat162float(h0) + __bfloat162float(l0)
                             + __bfloat162float(h1) + __bfloat162float(l1);
                rsum[mt][1] += __bfloat162float(h2) + __bfloat162float(l2)
                             + __bfloat162float(h3) + __bfloat162float(l3);
                php[mt][nt][0] = hpack(h0, h1); php[mt][nt][1] = hpack(h2, h3);
                plp[mt][nt][0] = hpack(l0, l1); plp[mt][nt][1] = hpack(l2, l3);
            }
#pragma unroll
        for (int mt = 0; mt < 2; mt++)
#pragma unroll
            for (int h = 0; h < 2; h++) {
                rsum[mt][h] += __shfl_xor_sync(0xffffffffu, rsum[mt][h], 1);
                rsum[mt][h] += __shfl_xor_sync(0xffffffffu, rsum[mt][h], 2);
            }
        if (tg == 0) {
#pragma unroll
            for (int mt = 0; mt < 2; mt++) {
                ssum[wn][row0 + mt * 16]     = rsum[mt][0];
                ssum[wn][row0 + mt * 16 + 8] = rsum[mt][1];
            }
        }
        __syncthreads();
        if (wn == 0 && tg == 0) {
#pragma unroll
            for (int mt = 0; mt < 2; mt++)
#pragma unroll
                for (int h = 0; h < 2; h++) {
                    int row = row0 + mt * 16 + h * 8;
                    l_row[row] = l_row[row] * corr[mt][h] + ssum[0][row] + ssum[1][row];
                    m_row[row] = mn[mt][h];
                }
        }
#pragma unroll
        for (int mt = 0; mt < 2; mt++)
#pragma unroll
            for (int nt = 0; nt < 8; nt++) {
                o[mt][nt][0] *= corr[mt][0]; o[mt][nt][1] *= corr[mt][0];
                o[mt][nt][2] *= corr[mt][1]; o[mt][nt][3] *= corr[mt][1];
            }
        // O_partial += P V (this group's 32 keys, K=16 chunks, N=64)
#pragma unroll
        for (int kc = 0; kc < 2; kc++) {
            uint32_t ah[2][4], al[2][4];
#pragma unroll
            for (int mt = 0; mt < 2; mt++) {
                ah[mt][0] = php[mt][2*kc][0];   ah[mt][1] = php[mt][2*kc][1];
                ah[mt][2] = php[mt][2*kc+1][0]; ah[mt][3] = php[mt][2*kc+1][1];
                al[mt][0] = plp[mt][2*kc][0];   al[mt][1] = plp[mt][2*kc][1];
                al[mt][2] = plp[mt][2*kc+1][0]; al[mt][3] = plp[mt][2*kc+1][1];
            }
#pragma unroll
            for (int nt = 0; nt < 8; nt++) {
                int vks = 2 * wn + kc;
                uint2 bh2 = *(const uint2*)(sm + BF_(49664, nt, vks, lane, 4));
                uint2 bl2 = *(const uint2*)(sm + BF_(58112, nt, vks, lane, 4));
#pragma unroll
                for (int mt = 0; mt < 2; mt++) {
                    mma_bf(o[mt][nt], ah[mt], bh2.x, bh2.y);
                    mma_bf(o[mt][nt], ah[mt], bl2.x, bl2.y);
                    mma_bf(o[mt][nt], al[mt], bh2.x, bh2.y);
                }
            }
        }
    }
    __syncthreads();
    float* ostg = (float*)sm;                         // [128][65]
    if (wn == 0) {
#pragma unroll
        for (int mt = 0; mt < 2; mt++)
#pragma unroll
            for (int nt = 0; nt < 8; nt++) {
                int r0 = wm * 32 + mt * 16 + g, c = nt * 8 + 2 * tg;
                ostg[r0 * 65 + c]           = o[mt][nt][0];
                ostg[r0 * 65 + c + 1]       = o[mt][nt][1];
                ostg[(r0 + 8) * 65 + c]     = o[mt][nt][2];
                ostg[(r0 + 8) * 65 + c + 1] = o[mt][nt][3];
            }
    }
    __syncthreads();
    if (wn == 1) {
#pragma unroll
        for (int mt = 0; mt < 2; mt++)
#pragma unroll
            for (int nt = 0; nt < 8; nt++) {
                int r0 = wm * 32 + mt * 16 + g, c = nt * 8 + 2 * tg;
                ostg[r0 * 65 + c]           += o[mt][nt][0];
                ostg[r0 * 65 + c + 1]       += o[mt][nt][1];
                ostg[(r0 + 8) * 65 + c]     += o[mt][nt][2];
                ostg[(r0 + 8) * 65 + c + 1] += o[mt][nt][3];
            }
    }
    __syncthreads();
    const int bb = bh >> 3, hh = bh & 7;
    for (int j = 0; j < 32; j++) {
        int idx = tid + j * 256; int d = idx & 63, rr = idx >> 6;
        ((uint32_t*)g_ao)[((bb << 10) + q0 + rr) * 512 + hh * 64 + d] =
            bpack(ostg[rr * 65 + d] / l_row[rr]);
    }
}

// ============ Kernel 3: out projection (identical to R15) ===================
__global__ __launch_bounds__(256, 2)
void gemm_out(const float* __restrict__ w, const float* __restrict__ bias,
              const float* __restrict__ x, float* __restrict__ out)
{
    extern __shared__ char sm[];
    const int tid = threadIdx.x, wid = tid >> 5, lane = tid & 31;
    const int g = lane >> 2, tg = lane & 3;
    const int wm = wid & 3, wn = wid >> 2;
    const int m0 = blockIdx.y * 128, o0 = blockIdx.x * 128;
    const int b = m0 >> 10, n0 = m0 & 1023;

    float acc[2][8][4];
#pragma unroll
    for (int i = 0; i < 2; i++)
#pragma unroll
        for (int j = 0; j < 8; j++)
#pragma unroll
            for (int q = 0; q < 4; q++) acc[i][j][q] = 0.f;

    for (int ck = 0; ck < 16; ck++) {
        __syncthreads();
#pragma unroll
        for (int it = 0; it < 8; it++) {
            int idx = tid + it * 256; int kp = idx & 15, m = idx >> 4;
            uint2 wv = *(const uint2*)((const uint32_t*)g_ao +
                        (size_t)(m0 + m) * 512 + ck * 32 + 2 * kp);
            int i2 = m >> 4, r = m & 15, ks = kp >> 3, kk = kp & 7;
            int reg = (r >> 3) | ((kk >> 2) << 1);
            int ls = (r & 7) * 4 + (kk & 3);
            *(uint32_t*)(sm + AF(0, i2, ks, ls, 2) + reg * 4) = __byte_perm(wv.x, wv.y, 0x5410);
            *(uint32_t*)(sm + AF(8192, i2, ks, ls, 2) + reg * 4) = __byte_perm(wv.x, wv.y, 0x7632);
        }
#pragma unroll
        for (int it = 0; it < 8; it++) {
            int idx = tid + it * 256; int oo = idx & 127, kp = idx >> 7;
            float v0 = w[(ck * 32 + 2 * kp) * 512 + o0 + oo];
            float v1 = w[(ck * 32 + 2 * kp + 1) * 512 + o0 + oo];
            bf h0, l0, h1, l1; bsplit(v0, h0, l0); bsplit(v1, h1, l1);
            int j2 = oo >> 3, g2 = oo & 7, ks = kp >> 3, kk = kp & 7;
            int reg = kk >> 2;
            int ls = g2 * 4 + (kk & 3);
            *(uint32_t*)(sm + BF_(16384, j2, ks, ls, 2) + reg * 4) = hpack(h0, h1);
            *(uint32_t*)(sm + BF_(24832, j2, ks, ls, 2) + reg * 4) = hpack(l0, l1);
        }
        __syncthreads();
#pragma unroll
        for (int ks = 0; ks < 2; ks++) {
            uint4 ahv[2], alv[2];
#pragma unroll
            for (int mt = 0; mt < 2; mt++) {
                int i2 = wm * 2 + mt;
                ahv[mt] = *(const uint4*)(sm + AF(0, i2, ks, lane, 2));
                alv[mt] = *(const uint4*)(sm + AF(8192, i2, ks, lane, 2));
            }
#pragma unroll
            for (int nt = 0; nt < 8; nt++) {
                int j2 = wn * 8 + nt;
                uint2 bh2 = *(const uint2*)(sm + BF_(16384, j2, ks, lane, 2));
                uint2 bl2 = *(const uint2*)(sm + BF_(24832, j2, ks, lane, 2));
#pragma unroll
                for (int mt = 0; mt < 2; mt++) {
                    mma_bf(acc[mt][nt], (const uint32_t*)&ahv[mt], bh2.x, bh2.y);
                    mma_bf(acc[mt][nt], (const uint32_t*)&ahv[mt], bl2.x, bl2.y);
                    mma_bf(acc[mt][nt], (const uint32_t*)&alv[mt], bh2.x, bh2.y);
                }
            }
        }
    }
    __syncthreads();
    float* stg = (float*)sm;
#pragma unroll
    for (int mt = 0; mt < 2; mt++)
#pragma unroll
        for (int nt = 0; nt < 8; nt++) {
            int r0 = wm * 32 + mt * 16 + g, c = wn * 64 + nt * 8 + 2 * tg;
            stg[r0 * 130 + c]           = acc[mt][nt][0];
            stg[r0 * 130 + c + 1]       = acc[mt][nt][1];
            stg[(r0 + 8) * 130 + c]     = acc[mt][nt][2];
            stg[(r0 + 8) * 130 + c + 1] = acc[mt][nt][3];
        }
    __syncthreads();
    for (int j = 0; j < 64; j++) {
        int idx = tid + j * 256; int rr = idx & 127, oc = idx >> 7;
        int oo = o0 + oc;
        int gi = ((b * 512 + oo) << 10) + n0 + rr;
        out[gi] = stg[rr * 130 + oc] + bias[oo] + x[gi];
    }
}

// ---------------------------------------------------------------------------
extern "C" void kernel_launch(void* const* d_in, const int* in_sizes, int n_in,
                              void* d_out, int out_size)
{
    const float* x      = (const float*)d_in[0];
    const float* w_proj = (const float*)d_in[1];
    const float* b_proj = (const float*)d_in[2];
    const float* w_out  = (const float*)d_in[3];
    const float* b_out  = (const float*)d_in[4];
    float* out = (float*)d_out;

    cudaFuncSetAttribute(gemm_qkv,    cudaFuncAttributeMaxDynamicSharedMemorySize, GEMM_SMEM);
    cudaFuncSetAttribute(attn_kernel, cudaFuncAttributeMaxDynamicSharedMemorySize, ATTN_SMEM);
    cudaFuncSetAttribute(gemm_out,    cudaFuncAttributeMaxDynamicSharedMemorySize, GEMM_SMEM);

    gemm_qkv<<<dim3(12, 128), 256, GEMM_SMEM>>>(x, w_proj, b_proj);
    attn_kernel<<<dim3(8, 128), 256, ATTN_SMEM>>>();
    gemm_out<<<dim3(4, 128), 256, GEMM_SMEM>>>(w_out, b_out, x, out);
}